// round 4
// baseline (speedup 1.0000x reference)
#include <cuda_runtime.h>
#include <math.h>

#define N_NODES 100000
#define N_EDGES 1000000
#define HID 64
#define EDIM 32
#define NSTEPS 4

// -------- device scratch (allocation-free: static __device__ globals) --------
__device__ __align__(128) float g_msg[(size_t)N_EDGES * HID];   // 256 MB
__device__ __align__(128) float g_agg[(size_t)N_NODES * HID];   // 25.6 MB
__device__ __align__(128) float g_W1t[EDIM * HID];              // [k][h] transposed
__device__ __align__(128) float g_W2t[HID * HID];               // [k2][d] transposed

// -------- transpose msg-MLP weights so the inner (unrolled) dim is contiguous --------
__global__ void prep_kernel(const float* __restrict__ W1, const float* __restrict__ W2) {
    int t = blockIdx.x * blockDim.x + threadIdx.x;
    if (t < EDIM * HID) {           // W1: [HID, EDIM] -> W1t[k*HID + h]
        int h = t % HID, k = t / HID;
        g_W1t[t] = W1[h * EDIM + k];
    }
    if (t < HID * HID) {            // W2: [HID, HID] -> W2t[k2*HID + d]
        int d = t % HID, k = t / HID;
        g_W2t[t] = W2[d * HID + k];
    }
}

// -------- K1: msg_base[e,:] = relu(ea[e,:] @ W1^T + b1) @ W2^T + b2 --------
__global__ __launch_bounds__(256) void msg_kernel(
    const float* __restrict__ ea, const float* __restrict__ b1,
    const float* __restrict__ b2)
{
    __shared__ float s_attr[256][EDIM + 1];
    const int e = blockIdx.x * 256 + threadIdx.x;
    const int base = blockIdx.x * 256 * EDIM;
    for (int i = threadIdx.x; i < 256 * EDIM; i += 256) {
        int r = i >> 5, c = i & 31;
        int gi = base + i;
        s_attr[r][c] = (gi < N_EDGES * EDIM) ? ea[gi] : 0.f;
    }
    __syncthreads();

    // layer 1: hid[h] = relu(sum_k attr[k] * W1t[k][h] + b1[h])
    float hid[HID];
    #pragma unroll
    for (int h = 0; h < HID; ++h) hid[h] = __ldg(&b1[h]);

    #pragma unroll 1
    for (int k = 0; k < EDIM; ++k) {
        float a = s_attr[threadIdx.x][k];
        const float4* w4 = reinterpret_cast<const float4*>(&g_W1t[k * HID]);
        #pragma unroll
        for (int h4 = 0; h4 < HID / 4; ++h4) {
            float4 w = __ldg(&w4[h4]);
            hid[h4 * 4 + 0] += a * w.x;
            hid[h4 * 4 + 1] += a * w.y;
            hid[h4 * 4 + 2] += a * w.z;
            hid[h4 * 4 + 3] += a * w.w;
        }
    }
    #pragma unroll
    for (int h = 0; h < HID; ++h) hid[h] = fmaxf(hid[h], 0.f);

    // layer 2 in 4 chunks of 16 outputs (out regs reused per chunk)
    float* outp = &g_msg[(size_t)e * HID];
    #pragma unroll 1
    for (int c = 0; c < 4; ++c) {
        float o[16];
        #pragma unroll
        for (int u = 0; u < 16; ++u) o[u] = __ldg(&b2[c * 16 + u]);

        #pragma unroll
        for (int k2 = 0; k2 < HID; ++k2) {
            float v = hid[k2];
            const float4* w4 = reinterpret_cast<const float4*>(&g_W2t[k2 * HID + c * 16]);
            #pragma unroll
            for (int u4 = 0; u4 < 4; ++u4) {
                float4 w = __ldg(&w4[u4]);
                o[u4 * 4 + 0] += v * w.x;
                o[u4 * 4 + 1] += v * w.y;
                o[u4 * 4 + 2] += v * w.z;
                o[u4 * 4 + 3] += v * w.w;
            }
        }
        if (e < N_EDGES) {
            float4* op = reinterpret_cast<float4*>(outp + c * 16);
            op[0] = make_float4(o[0],  o[1],  o[2],  o[3]);
            op[1] = make_float4(o[4],  o[5],  o[6],  o[7]);
            op[2] = make_float4(o[8],  o[9],  o[10], o[11]);
            op[3] = make_float4(o[12], o[13], o[14], o[15]);
        }
    }
}

// -------- K2: agg[i] += msg_base[e] * h[j], via vector reductions --------
// NOTE: edge_index arrives as int32 (harness converts int64 inputs to int32).
// 16 threads per edge, each owning one float4 lane; msg stream coalesced,
// h gather L2-resident, scatter via red.global.add.v4.f32 (16B/atomic).
__global__ __launch_bounds__(256) void scatter_kernel(
    const int* __restrict__ eidx, const float* __restrict__ h)
{
    long long t = (long long)blockIdx.x * 256 + threadIdx.x;
    int e = (int)(t >> 4);
    int q = (int)(t & 15);
    if (e >= N_EDGES) return;
    int dst = eidx[e];                   // edge_index[0] = i (aggregation target)
    int src = eidx[N_EDGES + e];         // edge_index[1] = j (gather source)
    if ((unsigned)dst >= N_NODES || (unsigned)src >= N_NODES) return;  // never taken if data sane

    float4 m  = *reinterpret_cast<const float4*>(&g_msg[(size_t)e * HID + q * 4]);
    float4 hv = __ldg(reinterpret_cast<const float4*>(&h[(size_t)src * HID + q * 4]));
    float4 r  = make_float4(m.x * hv.x, m.y * hv.y, m.z * hv.z, m.w * hv.w);
    float* p  = &g_agg[(size_t)dst * HID + q * 4];
    asm volatile("red.global.add.v4.f32 [%0], {%1, %2, %3, %4};"
                 :: "l"(p), "f"(r.x), "f"(r.y), "f"(r.z), "f"(r.w) : "memory");
}

// -------- K3: h = GRU(agg, h), persistent CTAs, weights resident in smem --------
// block = 256 threads = 64 dims x 4 node-groups; each thread does 8 nodes (NPT=8)
#define GRU_SMEM_FLOATS (2 * 192 * 65 + 2 * 32 * 64)
#define GRU_SMEM_BYTES  (GRU_SMEM_FLOATS * 4)

__global__ __launch_bounds__(256) void gru_kernel(
    const float* __restrict__ Wih, const float* __restrict__ bih,
    const float* __restrict__ Whh, const float* __restrict__ bhh,
    float* __restrict__ h)
{
    extern __shared__ float sm[];
    float* sWih = sm;                    // [192][65] padded (conflict-free)
    float* sWhh = sm + 192 * 65;
    float* sAgg = sWhh + 192 * 65;       // [32][64]
    float* sH   = sAgg + 32 * 64;        // [32][64]

    const int tid = threadIdx.x;
    const int d = tid & 63;
    const int g = tid >> 6;

    for (int i = tid; i < 192 * 64; i += 256) {
        int r = i >> 6, c = i & 63;
        sWih[r * 65 + c] = Wih[i];
        sWhh[r * 65 + c] = Whh[i];
    }
    const float bi_r = __ldg(&bih[d]), bi_z = __ldg(&bih[64 + d]), bi_n = __ldg(&bih[128 + d]);
    const float bh_r = __ldg(&bhh[d]), bh_z = __ldg(&bhh[64 + d]), bh_n = __ldg(&bhh[128 + d]);
    __syncthreads();

    const int ntiles = N_NODES / 32;     // 3125 (exact)
    for (int tile = blockIdx.x; tile < ntiles; tile += gridDim.x) {
        const int nb = tile * 32;
        for (int i = tid; i < 32 * 64; i += 256) {
            sAgg[i] = g_agg[(size_t)nb * 64 + i];
            sH[i]   = h[(size_t)nb * 64 + i];
        }
        __syncthreads();

        float ir[8], iz[8], in_[8], hr[8], hz[8], hn[8];
        #pragma unroll
        for (int j = 0; j < 8; ++j) { ir[j]=iz[j]=in_[j]=hr[j]=hz[j]=hn[j]=0.f; }

        #pragma unroll 2
        for (int k = 0; k < 64; ++k) {
            float w_ir = sWih[d * 65 + k];
            float w_iz = sWih[(64 + d) * 65 + k];
            float w_in = sWih[(128 + d) * 65 + k];
            float w_hr = sWhh[d * 65 + k];
            float w_hz = sWhh[(64 + d) * 65 + k];
            float w_hn = sWhh[(128 + d) * 65 + k];
            #pragma unroll
            for (int j = 0; j < 8; ++j) {
                float a  = sAgg[(g * 8 + j) * 64 + k];  // warp-broadcast
                float hh = sH[(g * 8 + j) * 64 + k];
                ir[j]  += w_ir * a;  iz[j] += w_iz * a;  in_[j] += w_in * a;
                hr[j]  += w_hr * hh; hz[j] += w_hz * hh; hn[j]  += w_hn * hh;
            }
        }

        #pragma unroll
        for (int j = 0; j < 8; ++j) {
            int n = g * 8 + j;
            float r  = 1.f / (1.f + expf(-(ir[j] + bi_r + hr[j] + bh_r)));
            float z  = 1.f / (1.f + expf(-(iz[j] + bi_z + hz[j] + bh_z)));
            float nn = tanhf(in_[j] + bi_n + r * (hn[j] + bh_n));
            float hp = sH[n * 64 + d];
            h[(size_t)(nb + n) * 64 + d] = (1.f - z) * nn + z * hp;  // coalesced
        }
        __syncthreads();
    }
}

// -------- launch --------
extern "C" void kernel_launch(void* const* d_in, const int* in_sizes, int n_in,
                              void* d_out, int out_size)
{
    const float* h0   = (const float*)d_in[0];
    const float* ea   = (const float*)d_in[1];
    const int*   eidx = (const int*)d_in[2];     // int64 inputs arrive as int32
    const float* W1   = (const float*)d_in[3];
    const float* b1   = (const float*)d_in[4];
    const float* W2   = (const float*)d_in[5];
    const float* b2   = (const float*)d_in[6];
    const float* Wih  = (const float*)d_in[7];
    const float* bih  = (const float*)d_in[8];
    const float* Whh  = (const float*)d_in[9];
    const float* bhh  = (const float*)d_in[10];
    float* h = (float*)d_out;

    cudaFuncSetAttribute(gru_kernel, cudaFuncAttributeMaxDynamicSharedMemorySize,
                         GRU_SMEM_BYTES);

    void* aggPtr = nullptr;
    cudaGetSymbolAddress(&aggPtr, g_agg);

    // h_cur lives in d_out; updated in place each step
    cudaMemcpyAsync(h, h0, (size_t)N_NODES * HID * sizeof(float),
                    cudaMemcpyDeviceToDevice, 0);

    prep_kernel<<<16, 256>>>(W1, W2);
    msg_kernel<<<(N_EDGES + 255) / 256, 256>>>(ea, b1, b2);

    for (int s = 0; s < NSTEPS; ++s) {
        cudaMemsetAsync(aggPtr, 0, (size_t)N_NODES * HID * sizeof(float), 0);
        scatter_kernel<<<(N_EDGES * 16) / 256, 256>>>(eidx, h);
        gru_kernel<<<152, 256, GRU_SMEM_BYTES>>>(Wih, bih, Whh, bhh, h);
    }
}

// round 5
// speedup vs baseline: 1.4935x; 1.4935x over previous
#include <cuda_runtime.h>
#include <math.h>

#define N_NODES 100000
#define N_EDGES 1000000
#define HID 64
#define EDIM 32
#define NSTEPS 4

// -------- device scratch (allocation-free: static __device__ globals) --------
__device__ __align__(128) float g_msg[(size_t)N_EDGES * HID];   // 256 MB (CSR-ordered)
__device__ __align__(128) float g_agg[(size_t)N_NODES * HID];   // 25.6 MB
__device__ __align__(128) float g_W1t[EDIM * HID];
__device__ __align__(128) float g_W2t[HID * HID];
// CSR structures (rebuilt every launch; edge_index is launch-invariant data)
__device__ __align__(128) int g_count[N_NODES];
__device__ __align__(128) int g_rowstart[N_NODES + 1];
__device__ __align__(128) int g_cursor[N_NODES];
__device__ __align__(128) int g_src[N_EDGES];     // src node per CSR slot
__device__ __align__(128) int g_eperm[N_EDGES];   // edge -> CSR slot

// -------- weight transpose --------
__global__ void prep_kernel(const float* __restrict__ W1, const float* __restrict__ W2) {
    int t = blockIdx.x * blockDim.x + threadIdx.x;
    if (t < EDIM * HID) {           // W1: [HID, EDIM] -> W1t[k*HID + h]
        int h = t % HID, k = t / HID;
        g_W1t[t] = W1[h * EDIM + k];
    }
    if (t < HID * HID) {            // W2: [HID, HID] -> W2t[k2*HID + d]
        int d = t % HID, k = t / HID;
        g_W2t[t] = W2[d * HID + k];
    }
}

// -------- CSR build: histogram --------
__global__ __launch_bounds__(256) void hist_kernel(const int* __restrict__ eidx) {
    int t = blockIdx.x * 256 + threadIdx.x;
    if (t >= N_EDGES) return;
    int dst = eidx[t];
    if ((unsigned)dst < N_NODES) atomicAdd(&g_count[dst], 1);
}

// -------- CSR build: exclusive scan (single block, 1024 threads) --------
__global__ __launch_bounds__(1024) void scan_kernel() {
    __shared__ int s[1024];
    const int T = 1024;
    const int tid = threadIdx.x;
    const int chunk = (N_NODES + T - 1) / T;   // 98
    const int start = tid * chunk;
    int sum = 0;
    for (int i = 0; i < chunk; ++i) {
        int idx = start + i;
        if (idx < N_NODES) sum += g_count[idx];
    }
    s[tid] = sum;
    __syncthreads();
    for (int off = 1; off < T; off <<= 1) {     // Hillis-Steele inclusive scan
        int v = 0;
        if (tid >= off) v = s[tid - off];
        __syncthreads();
        if (tid >= off) s[tid] += v;
        __syncthreads();
    }
    int run = (tid == 0) ? 0 : s[tid - 1];
    for (int i = 0; i < chunk; ++i) {
        int idx = start + i;
        if (idx < N_NODES) {
            g_rowstart[idx] = run;
            g_cursor[idx]   = run;
            run += g_count[idx];
        }
    }
    if (tid == T - 1) g_rowstart[N_NODES] = run;
}

// -------- CSR build: bucket placement --------
__global__ __launch_bounds__(256) void place_kernel(const int* __restrict__ eidx) {
    int t = blockIdx.x * 256 + threadIdx.x;
    if (t >= N_EDGES) return;
    int dst = eidx[t];
    int src = eidx[N_EDGES + t];
    if ((unsigned)dst >= N_NODES || (unsigned)src >= N_NODES) { g_eperm[t] = 0; return; }
    int pos = atomicAdd(&g_cursor[dst], 1);
    g_src[pos] = src;
    g_eperm[t] = pos;
}

// -------- K1: msg MLP; writes CSR-permuted rows; weights staged in smem --------
__global__ __launch_bounds__(256) void msg_kernel(
    const float* __restrict__ ea, const float* __restrict__ b1,
    const float* __restrict__ b2)
{
    __shared__ float s_attr[256][EDIM + 1];
    __shared__ float sW1[EDIM * HID];   // 8 KB
    __shared__ float sW2[HID * HID];    // 16 KB
    const int e = blockIdx.x * 256 + threadIdx.x;
    const int base = blockIdx.x * 256 * EDIM;

    for (int i = threadIdx.x; i < EDIM * HID; i += 256) sW1[i] = g_W1t[i];
    for (int i = threadIdx.x; i < HID * HID; i += 256)  sW2[i] = g_W2t[i];
    for (int i = threadIdx.x; i < 256 * EDIM; i += 256) {
        int r = i >> 5, c = i & 31;
        int gi = base + i;
        s_attr[r][c] = (gi < N_EDGES * EDIM) ? ea[gi] : 0.f;
    }
    __syncthreads();

    const int slot = (e < N_EDGES) ? g_eperm[e] : 0;

    float hid[HID];
    #pragma unroll
    for (int h = 0; h < HID; ++h) hid[h] = __ldg(&b1[h]);

    #pragma unroll 1
    for (int k = 0; k < EDIM; ++k) {
        float a = s_attr[threadIdx.x][k];
        const float4* w4 = reinterpret_cast<const float4*>(&sW1[k * HID]);
        #pragma unroll
        for (int h4 = 0; h4 < HID / 4; ++h4) {
            float4 w = w4[h4];
            hid[h4 * 4 + 0] += a * w.x;
            hid[h4 * 4 + 1] += a * w.y;
            hid[h4 * 4 + 2] += a * w.z;
            hid[h4 * 4 + 3] += a * w.w;
        }
    }
    #pragma unroll
    for (int h = 0; h < HID; ++h) hid[h] = fmaxf(hid[h], 0.f);

    float* outp = &g_msg[(size_t)slot * HID];
    #pragma unroll 1
    for (int c = 0; c < 4; ++c) {
        float o[16];
        #pragma unroll
        for (int u = 0; u < 16; ++u) o[u] = __ldg(&b2[c * 16 + u]);

        #pragma unroll
        for (int k2 = 0; k2 < HID; ++k2) {
            float v = hid[k2];
            const float4* w4 = reinterpret_cast<const float4*>(&sW2[k2 * HID + c * 16]);
            #pragma unroll
            for (int u4 = 0; u4 < 4; ++u4) {
                float4 w = w4[u4];
                o[u4 * 4 + 0] += v * w.x;
                o[u4 * 4 + 1] += v * w.y;
                o[u4 * 4 + 2] += v * w.z;
                o[u4 * 4 + 3] += v * w.w;
            }
        }
        if (e < N_EDGES) {
            float4* op = reinterpret_cast<float4*>(outp + c * 16);
            op[0] = make_float4(o[0],  o[1],  o[2],  o[3]);
            op[1] = make_float4(o[4],  o[5],  o[6],  o[7]);
            op[2] = make_float4(o[8],  o[9],  o[10], o[11]);
            op[3] = make_float4(o[12], o[13], o[14], o[15]);
        }
    }
}

// -------- K2: gather aggregation (no atomics, no memset) --------
// 16 threads per node, each owning one float4 lane; msg stream is sequential
// (CSR-ordered), h gather L2-resident, agg written exactly once.
__global__ __launch_bounds__(256) void gather_kernel(const float* __restrict__ h) {
    int t = blockIdx.x * 256 + threadIdx.x;
    int n = t >> 4;
    int q = t & 15;
    if (n >= N_NODES) return;
    int p  = g_rowstart[n];
    int re = g_rowstart[n + 1];
    float4 acc = make_float4(0.f, 0.f, 0.f, 0.f);
    // 2-way unroll for MLP
    for (; p + 1 < re; p += 2) {
        float4 m0 = *reinterpret_cast<const float4*>(&g_msg[(size_t)p * HID + q * 4]);
        float4 m1 = *reinterpret_cast<const float4*>(&g_msg[(size_t)(p + 1) * HID + q * 4]);
        int s0 = __ldg(&g_src[p]);
        int s1 = __ldg(&g_src[p + 1]);
        float4 h0 = __ldg(reinterpret_cast<const float4*>(&h[(size_t)s0 * HID + q * 4]));
        float4 h1 = __ldg(reinterpret_cast<const float4*>(&h[(size_t)s1 * HID + q * 4]));
        acc.x += m0.x * h0.x; acc.y += m0.y * h0.y; acc.z += m0.z * h0.z; acc.w += m0.w * h0.w;
        acc.x += m1.x * h1.x; acc.y += m1.y * h1.y; acc.z += m1.z * h1.z; acc.w += m1.w * h1.w;
    }
    if (p < re) {
        float4 m = *reinterpret_cast<const float4*>(&g_msg[(size_t)p * HID + q * 4]);
        int s = __ldg(&g_src[p]);
        float4 hv = __ldg(reinterpret_cast<const float4*>(&h[(size_t)s * HID + q * 4]));
        acc.x += m.x * hv.x; acc.y += m.y * hv.y; acc.z += m.z * hv.z; acc.w += m.w * hv.w;
    }
    *reinterpret_cast<float4*>(&g_agg[(size_t)n * HID + q * 4]) = acc;
}

// -------- K3: h = GRU(agg, h); 512 threads, 64-node tiles, weights in smem --------
#define GRU_TILE 64
#define GRU_SMEM_FLOATS (2 * 192 * 65 + 2 * GRU_TILE * 64)
#define GRU_SMEM_BYTES  (GRU_SMEM_FLOATS * 4)

__global__ __launch_bounds__(512) void gru_kernel(
    const float* __restrict__ Wih, const float* __restrict__ bih,
    const float* __restrict__ Whh, const float* __restrict__ bhh,
    float* __restrict__ h)
{
    extern __shared__ float sm[];
    float* sWih = sm;                     // [192][65] padded
    float* sWhh = sm + 192 * 65;
    float* sAgg = sWhh + 192 * 65;        // [64][64]
    float* sH   = sAgg + GRU_TILE * 64;   // [64][64]

    const int tid = threadIdx.x;
    const int d = tid & 63;
    const int g = tid >> 6;               // 0..7

    for (int i = tid; i < 192 * 64; i += 512) {
        int r = i >> 6, c = i & 63;
        sWih[r * 65 + c] = Wih[i];
        sWhh[r * 65 + c] = Whh[i];
    }
    const float bi_r = __ldg(&bih[d]), bi_z = __ldg(&bih[64 + d]), bi_n = __ldg(&bih[128 + d]);
    const float bh_r = __ldg(&bhh[d]), bh_z = __ldg(&bhh[64 + d]), bh_n = __ldg(&bhh[128 + d]);
    __syncthreads();

    const int ntiles = (N_NODES + GRU_TILE - 1) / GRU_TILE;   // 1563
    for (int tile = blockIdx.x; tile < ntiles; tile += gridDim.x) {
        const int nb = tile * GRU_TILE;
        for (int i = tid; i < GRU_TILE * 64; i += 512) {
            size_t gi = (size_t)nb * 64 + i;
            bool ok = gi < (size_t)N_NODES * 64;
            sAgg[i] = ok ? g_agg[gi] : 0.f;
            sH[i]   = ok ? h[gi] : 0.f;
        }
        __syncthreads();

        float ir[8], iz[8], in_[8], hr[8], hz[8], hn[8];
        #pragma unroll
        for (int j = 0; j < 8; ++j) { ir[j]=iz[j]=in_[j]=hr[j]=hz[j]=hn[j]=0.f; }

        #pragma unroll 2
        for (int k = 0; k < 64; ++k) {
            float w_ir = sWih[d * 65 + k];
            float w_iz = sWih[(64 + d) * 65 + k];
            float w_in = sWih[(128 + d) * 65 + k];
            float w_hr = sWhh[d * 65 + k];
            float w_hz = sWhh[(64 + d) * 65 + k];
            float w_hn = sWhh[(128 + d) * 65 + k];
            #pragma unroll
            for (int j = 0; j < 8; ++j) {
                float a  = sAgg[(g * 8 + j) * 64 + k];
                float hh = sH[(g * 8 + j) * 64 + k];
                ir[j]  += w_ir * a;  iz[j] += w_iz * a;  in_[j] += w_in * a;
                hr[j]  += w_hr * hh; hz[j] += w_hz * hh; hn[j]  += w_hn * hh;
            }
        }

        #pragma unroll
        for (int j = 0; j < 8; ++j) {
            int n = g * 8 + j;
            if (nb + n < N_NODES) {
                float r  = 1.f / (1.f + expf(-(ir[j] + bi_r + hr[j] + bh_r)));
                float z  = 1.f / (1.f + expf(-(iz[j] + bi_z + hz[j] + bh_z)));
                float nn = tanhf(in_[j] + bi_n + r * (hn[j] + bh_n));
                float hp = sH[n * 64 + d];
                h[(size_t)(nb + n) * 64 + d] = (1.f - z) * nn + z * hp;
            }
        }
        __syncthreads();
    }
}

// -------- launch --------
extern "C" void kernel_launch(void* const* d_in, const int* in_sizes, int n_in,
                              void* d_out, int out_size)
{
    const float* h0   = (const float*)d_in[0];
    const float* ea   = (const float*)d_in[1];
    const int*   eidx = (const int*)d_in[2];     // int64 inputs arrive as int32
    const float* W1   = (const float*)d_in[3];
    const float* b1   = (const float*)d_in[4];
    const float* W2   = (const float*)d_in[5];
    const float* b2   = (const float*)d_in[6];
    const float* Wih  = (const float*)d_in[7];
    const float* bih  = (const float*)d_in[8];
    const float* Whh  = (const float*)d_in[9];
    const float* bhh  = (const float*)d_in[10];
    float* h = (float*)d_out;

    cudaFuncSetAttribute(gru_kernel, cudaFuncAttributeMaxDynamicSharedMemorySize,
                         GRU_SMEM_BYTES);

    void* countPtr = nullptr;
    cudaGetSymbolAddress(&countPtr, g_count);

    cudaMemcpyAsync(h, h0, (size_t)N_NODES * HID * sizeof(float),
                    cudaMemcpyDeviceToDevice, 0);

    // CSR build (edge_index is launch-invariant)
    cudaMemsetAsync(countPtr, 0, N_NODES * sizeof(int), 0);
    hist_kernel<<<(N_EDGES + 255) / 256, 256>>>(eidx);
    scan_kernel<<<1, 1024>>>();
    place_kernel<<<(N_EDGES + 255) / 256, 256>>>(eidx);

    prep_kernel<<<16, 256>>>(W1, W2);
    msg_kernel<<<(N_EDGES + 255) / 256, 256>>>(ea, b1, b2);

    for (int s = 0; s < NSTEPS; ++s) {
        gather_kernel<<<(N_NODES * 16 + 255) / 256, 256>>>(h);
        gru_kernel<<<152, 512, GRU_SMEM_BYTES>>>(Wih, bih, Whh, bhh, h);
    }
}

// round 6
// speedup vs baseline: 1.5144x; 1.0140x over previous
#include <cuda_runtime.h>
#include <math.h>

#define N_NODES 100000
#define N_EDGES 1000000
#define HID 64
#define EDIM 32
#define NSTEPS 4

typedef unsigned long long u64;

// ---- packed f32x2 helpers (FFMA2: only reachable via PTX fma.rn.f32x2) ----
__device__ __forceinline__ u64 fma2(u64 a, u64 b, u64 c) {
    u64 d; asm("fma.rn.f32x2 %0, %1, %2, %3;" : "=l"(d) : "l"(a), "l"(b), "l"(c)); return d;
}
__device__ __forceinline__ u64 pack2(float lo, float hi) {
    u64 d; asm("mov.b64 %0, {%1, %2};" : "=l"(d) : "f"(lo), "f"(hi)); return d;
}
__device__ __forceinline__ void unpack2(u64 v, float& lo, float& hi) {
    asm("mov.b64 {%0, %1}, %2;" : "=f"(lo), "=f"(hi) : "l"(v));
}
__device__ __forceinline__ float fsigmoid(float x) {
    return __fdividef(1.f, 1.f + __expf(-x));
}
__device__ __forceinline__ float ftanh(float x) {
    float e = __expf(-2.f * x);
    return __fdividef(1.f - e, 1.f + e);
}

// -------- device scratch (allocation-free: static __device__ globals) --------
__device__ __align__(128) float g_msg[(size_t)N_EDGES * HID];   // 256 MB (CSR-ordered)
__device__ __align__(128) float g_agg[(size_t)N_NODES * HID];   // 25.6 MB
__device__ __align__(128) int g_count[N_NODES];
__device__ __align__(128) int g_rowstart[N_NODES + 1];
__device__ __align__(128) int g_cursor[N_NODES];
__device__ __align__(128) int g_src[N_EDGES];
__device__ __align__(128) int g_eperm[N_EDGES];

// -------- CSR build: histogram --------
__global__ __launch_bounds__(256) void hist_kernel(const int* __restrict__ eidx) {
    int t = blockIdx.x * 256 + threadIdx.x;
    if (t >= N_EDGES) return;
    int dst = eidx[t];
    if ((unsigned)dst < N_NODES) atomicAdd(&g_count[dst], 1);
}

// -------- CSR build: exclusive scan (single block) --------
__global__ __launch_bounds__(1024) void scan_kernel() {
    __shared__ int s[1024];
    const int T = 1024;
    const int tid = threadIdx.x;
    const int chunk = (N_NODES + T - 1) / T;
    const int start = tid * chunk;
    int sum = 0;
    for (int i = 0; i < chunk; ++i) {
        int idx = start + i;
        if (idx < N_NODES) sum += g_count[idx];
    }
    s[tid] = sum;
    __syncthreads();
    for (int off = 1; off < T; off <<= 1) {
        int v = 0;
        if (tid >= off) v = s[tid - off];
        __syncthreads();
        if (tid >= off) s[tid] += v;
        __syncthreads();
    }
    int run = (tid == 0) ? 0 : s[tid - 1];
    for (int i = 0; i < chunk; ++i) {
        int idx = start + i;
        if (idx < N_NODES) {
            g_rowstart[idx] = run;
            g_cursor[idx]   = run;
            run += g_count[idx];
        }
    }
    if (tid == T - 1) g_rowstart[N_NODES] = run;
}

// -------- CSR build: bucket placement --------
__global__ __launch_bounds__(256) void place_kernel(const int* __restrict__ eidx) {
    int t = blockIdx.x * 256 + threadIdx.x;
    if (t >= N_EDGES) return;
    int dst = eidx[t];
    int src = eidx[N_EDGES + t];
    if ((unsigned)dst >= N_NODES || (unsigned)src >= N_NODES) { g_eperm[t] = 0; return; }
    int pos = atomicAdd(&g_cursor[dst], 1);
    g_src[pos] = src;
    g_eperm[t] = pos;
}

// -------- K1: msg MLP via f32x2; transposes weights during smem staging --------
__global__ __launch_bounds__(256) void msg_kernel(
    const float* __restrict__ ea,
    const float* __restrict__ W1, const float* __restrict__ b1,
    const float* __restrict__ W2, const float* __restrict__ b2)
{
    __shared__ float s_attr[256][EDIM + 1];
    __shared__ float sW1[EDIM * HID];   // [k][h]
    __shared__ float sW2[HID * HID];    // [k2][d]
    const int e = blockIdx.x * 256 + threadIdx.x;
    const int base = blockIdx.x * 256 * EDIM;

    // stage + transpose weights (one-time per CTA)
    for (int i = threadIdx.x; i < EDIM * HID; i += 256) {
        int k = i >> 6, h = i & 63;
        sW1[i] = W1[h * EDIM + k];
    }
    for (int i = threadIdx.x; i < HID * HID; i += 256) {
        int k2 = i >> 6, d = i & 63;
        sW2[i] = W2[d * HID + k2];
    }
    for (int i = threadIdx.x; i < 256 * EDIM; i += 256) {
        int r = i >> 5, c = i & 31;
        int gi = base + i;
        s_attr[r][c] = (gi < N_EDGES * EDIM) ? ea[gi] : 0.f;
    }
    __syncthreads();

    const int slot = (e < N_EDGES) ? g_eperm[e] : 0;

    // layer 1: paired over h
    u64 hid2[HID / 2];
    const u64* b1p = reinterpret_cast<const u64*>(b1);
    #pragma unroll
    for (int h2 = 0; h2 < HID / 2; ++h2) hid2[h2] = __ldg(&b1p[h2]);

    #pragma unroll 1
    for (int k = 0; k < EDIM; ++k) {
        float a = s_attr[threadIdx.x][k];
        u64 a2 = pack2(a, a);
        const u64* w2 = reinterpret_cast<const u64*>(&sW1[k * HID]);
        #pragma unroll
        for (int h2 = 0; h2 < HID / 2; ++h2)
            hid2[h2] = fma2(a2, w2[h2], hid2[h2]);
    }
    float hid[HID];
    #pragma unroll
    for (int h2 = 0; h2 < HID / 2; ++h2) {
        float lo, hi; unpack2(hid2[h2], lo, hi);
        hid[2 * h2]     = fmaxf(lo, 0.f);
        hid[2 * h2 + 1] = fmaxf(hi, 0.f);
    }

    // layer 2: 4 chunks of 16 outputs (8 pairs each)
    float* outp = &g_msg[(size_t)slot * HID];
    const u64* b2p = reinterpret_cast<const u64*>(b2);
    #pragma unroll 1
    for (int c = 0; c < 4; ++c) {
        u64 o2[8];
        #pragma unroll
        for (int u = 0; u < 8; ++u) o2[u] = __ldg(&b2p[c * 8 + u]);

        #pragma unroll
        for (int k2 = 0; k2 < HID; ++k2) {
            u64 v2 = pack2(hid[k2], hid[k2]);
            const u64* w2 = reinterpret_cast<const u64*>(&sW2[k2 * HID + c * 16]);
            #pragma unroll
            for (int u = 0; u < 8; ++u)
                o2[u] = fma2(v2, w2[u], o2[u]);
        }
        if (e < N_EDGES) {
            ulonglong2* op = reinterpret_cast<ulonglong2*>(outp + c * 16);
            op[0] = make_ulonglong2(o2[0], o2[1]);
            op[1] = make_ulonglong2(o2[2], o2[3]);
            op[2] = make_ulonglong2(o2[4], o2[5]);
            op[3] = make_ulonglong2(o2[6], o2[7]);
        }
    }
}

// -------- K2: gather aggregation (no atomics) --------
__global__ __launch_bounds__(256) void gather_kernel(const float* __restrict__ h) {
    int t = blockIdx.x * 256 + threadIdx.x;
    int n = t >> 4;
    int q = t & 15;
    if (n >= N_NODES) return;
    int p  = g_rowstart[n];
    int re = g_rowstart[n + 1];
    float4 acc = make_float4(0.f, 0.f, 0.f, 0.f);
    for (; p + 1 < re; p += 2) {
        float4 m0 = *reinterpret_cast<const float4*>(&g_msg[(size_t)p * HID + q * 4]);
        float4 m1 = *reinterpret_cast<const float4*>(&g_msg[(size_t)(p + 1) * HID + q * 4]);
        int s0 = __ldg(&g_src[p]);
        int s1 = __ldg(&g_src[p + 1]);
        float4 h0 = __ldg(reinterpret_cast<const float4*>(&h[(size_t)s0 * HID + q * 4]));
        float4 h1 = __ldg(reinterpret_cast<const float4*>(&h[(size_t)s1 * HID + q * 4]));
        acc.x += m0.x * h0.x; acc.y += m0.y * h0.y; acc.z += m0.z * h0.z; acc.w += m0.w * h0.w;
        acc.x += m1.x * h1.x; acc.y += m1.y * h1.y; acc.z += m1.z * h1.z; acc.w += m1.w * h1.w;
    }
    if (p < re) {
        float4 m = *reinterpret_cast<const float4*>(&g_msg[(size_t)p * HID + q * 4]);
        int s = __ldg(&g_src[p]);
        float4 hv = __ldg(reinterpret_cast<const float4*>(&h[(size_t)s * HID + q * 4]));
        acc.x += m.x * hv.x; acc.y += m.y * hv.y; acc.z += m.z * hv.z; acc.w += m.w * hv.w;
    }
    *reinterpret_cast<float4*>(&g_agg[(size_t)n * HID + q * 4]) = acc;
}

// -------- K3: GRU via f32x2, node-pair accumulators, transposed data tiles --------
#define WPAD 67   // 67 mod 32 = 3, coprime -> conflict-free weight columns
#define DPAD 68   // 68*4 mod 16 = 0 -> 16B-aligned ulonglong2 rows
#define GRU_TILE 64
#define GRU_SMEM_FLOATS (2 * 192 * WPAD + 2 * GRU_TILE * DPAD)
#define GRU_SMEM_BYTES  (GRU_SMEM_FLOATS * 4)

__global__ __launch_bounds__(512) void gru_kernel(
    const float* __restrict__ Wih, const float* __restrict__ bih,
    const float* __restrict__ Whh, const float* __restrict__ bhh,
    float* __restrict__ h)
{
    extern __shared__ float sm[];
    float* sWih  = sm;                        // [192][WPAD]  row = gate*64+d, col = k
    float* sWhh  = sWih + 192 * WPAD;
    float* sAggT = sWhh + 192 * WPAD;         // [64][DPAD]   row = k, col = node
    float* sHT   = sAggT + GRU_TILE * DPAD;

    const int tid = threadIdx.x;
    const int d = tid & 63;
    const int g = tid >> 6;                   // 0..7, 8 nodes each

    for (int i = tid; i < 192 * 64; i += 512) {
        int r = i >> 6, c = i & 63;
        sWih[r * WPAD + c] = Wih[i];
        sWhh[r * WPAD + c] = Whh[i];
    }
    const float bi_r = __ldg(&bih[d]), bi_z = __ldg(&bih[64 + d]), bi_n = __ldg(&bih[128 + d]);
    const float bh_r = __ldg(&bhh[d]), bh_z = __ldg(&bhh[64 + d]), bh_n = __ldg(&bhh[128 + d]);
    const u64 brz2 = pack2(bi_r + bh_r, bi_r + bh_r);
    const u64 bzz2 = pack2(bi_z + bh_z, bi_z + bh_z);
    const u64 bin2 = pack2(bi_n, bi_n);
    const u64 bhn2 = pack2(bh_n, bh_n);
    __syncthreads();

    const int ntiles = (N_NODES + GRU_TILE - 1) / GRU_TILE;   // 1563
    for (int tile = blockIdx.x; tile < ntiles; tile += gridDim.x) {
        const int nb = tile * GRU_TILE;
        // stage transposed [k][node]
        for (int i = tid; i < GRU_TILE * 64; i += 512) {
            int node = i >> 6, k = i & 63;
            bool ok = (nb + node) < N_NODES;
            size_t gi = (size_t)(nb + node) * 64 + k;
            sAggT[k * DPAD + node] = ok ? g_agg[gi] : 0.f;
            sHT[k * DPAD + node]   = ok ? h[gi] : 0.f;
        }
        __syncthreads();

        u64 acc_r[4], acc_z[4], acc_in[4], acc_hn[4];
        #pragma unroll
        for (int jp = 0; jp < 4; ++jp) {
            acc_r[jp] = brz2; acc_z[jp] = bzz2; acc_in[jp] = bin2; acc_hn[jp] = bhn2;
        }

        #pragma unroll 2
        for (int k = 0; k < 64; ++k) {
            float wir = sWih[d * WPAD + k];
            float wiz = sWih[(64 + d) * WPAD + k];
            float win = sWih[(128 + d) * WPAD + k];
            float whr = sWhh[d * WPAD + k];
            float whz = sWhh[(64 + d) * WPAD + k];
            float whn = sWhh[(128 + d) * WPAD + k];
            u64 wir2 = pack2(wir, wir), wiz2 = pack2(wiz, wiz), win2 = pack2(win, win);
            u64 whr2 = pack2(whr, whr), whz2 = pack2(whz, whz), whn2 = pack2(whn, whn);
            const ulonglong2* aT = reinterpret_cast<const ulonglong2*>(&sAggT[k * DPAD + g * 8]);
            const ulonglong2* hT = reinterpret_cast<const ulonglong2*>(&sHT[k * DPAD + g * 8]);
            #pragma unroll
            for (int jq = 0; jq < 2; ++jq) {
                ulonglong2 aa = aT[jq];          // broadcast LDS.128 (nodes 4jq..4jq+3)
                ulonglong2 hh = hT[jq];
                acc_r[2*jq]   = fma2(wir2, aa.x, acc_r[2*jq]);
                acc_r[2*jq]   = fma2(whr2, hh.x, acc_r[2*jq]);
                acc_z[2*jq]   = fma2(wiz2, aa.x, acc_z[2*jq]);
                acc_z[2*jq]   = fma2(whz2, hh.x, acc_z[2*jq]);
                acc_in[2*jq]  = fma2(win2, aa.x, acc_in[2*jq]);
                acc_hn[2*jq]  = fma2(whn2, hh.x, acc_hn[2*jq]);
                acc_r[2*jq+1] = fma2(wir2, aa.y, acc_r[2*jq+1]);
                acc_r[2*jq+1] = fma2(whr2, hh.y, acc_r[2*jq+1]);
                acc_z[2*jq+1] = fma2(wiz2, aa.y, acc_z[2*jq+1]);
                acc_z[2*jq+1] = fma2(whz2, hh.y, acc_z[2*jq+1]);
                acc_in[2*jq+1]= fma2(win2, aa.y, acc_in[2*jq+1]);
                acc_hn[2*jq+1]= fma2(whn2, hh.y, acc_hn[2*jq+1]);
            }
        }

        #pragma unroll
        for (int jp = 0; jp < 4; ++jp) {
            float r0, r1, z0, z1, n0, n1, hn0, hn1;
            unpack2(acc_r[jp], r0, r1);
            unpack2(acc_z[jp], z0, z1);
            unpack2(acc_in[jp], n0, n1);
            unpack2(acc_hn[jp], hn0, hn1);
            int na = g * 8 + 2 * jp;
            #pragma unroll
            for (int half = 0; half < 2; ++half) {
                int n = na + half;
                if (nb + n < N_NODES) {
                    float rv  = fsigmoid(half ? r1 : r0);
                    float zv  = fsigmoid(half ? z1 : z0);
                    float nnv = ftanh((half ? n1 : n0) + rv * (half ? hn1 : hn0));
                    float hp  = sHT[d * DPAD + n];
                    h[(size_t)(nb + n) * 64 + d] = (1.f - zv) * nnv + zv * hp;
                }
            }
        }
        __syncthreads();
    }
}

// -------- launch --------
extern "C" void kernel_launch(void* const* d_in, const int* in_sizes, int n_in,
                              void* d_out, int out_size)
{
    const float* h0   = (const float*)d_in[0];
    const float* ea   = (const float*)d_in[1];
    const int*   eidx = (const int*)d_in[2];     // int64 inputs arrive as int32
    const float* W1   = (const float*)d_in[3];
    const float* b1   = (const float*)d_in[4];
    const float* W2   = (const float*)d_in[5];
    const float* b2   = (const float*)d_in[6];
    const float* Wih  = (const float*)d_in[7];
    const float* bih  = (const float*)d_in[8];
    const float* Whh  = (const float*)d_in[9];
    const float* bhh  = (const float*)d_in[10];
    float* h = (float*)d_out;

    cudaFuncSetAttribute(gru_kernel, cudaFuncAttributeMaxDynamicSharedMemorySize,
                         GRU_SMEM_BYTES);

    void* countPtr = nullptr;
    cudaGetSymbolAddress(&countPtr, g_count);

    cudaMemcpyAsync(h, h0, (size_t)N_NODES * HID * sizeof(float),
                    cudaMemcpyDeviceToDevice, 0);

    // CSR build (edge_index is launch-invariant)
    cudaMemsetAsync(countPtr, 0, N_NODES * sizeof(int), 0);
    hist_kernel<<<(N_EDGES + 255) / 256, 256>>>(eidx);
    scan_kernel<<<1, 1024>>>();
    place_kernel<<<(N_EDGES + 255) / 256, 256>>>(eidx);

    // launch slot 6 -> ncu (-s 5 -c 1) captures msg_kernel this round
    msg_kernel<<<(N_EDGES + 255) / 256, 256>>>(ea, W1, b1, W2, b2);

    for (int s = 0; s < NSTEPS; ++s) {
        gather_kernel<<<(N_NODES * 16 + 255) / 256, 256>>>(h);
        gru_kernel<<<152, 512, GRU_SMEM_BYTES>>>(Wih, bih, Whh, bhh, h);
    }
}

// round 7
// speedup vs baseline: 1.5740x; 1.0394x over previous
#include <cuda_runtime.h>
#include <math.h>

#define N_NODES 100000
#define N_EDGES 1000000
#define HID 64
#define EDIM 32
#define NSTEPS 4

typedef unsigned long long u64;

// ---- packed f32x2 helpers (FFMA2: only reachable via PTX fma.rn.f32x2) ----
__device__ __forceinline__ u64 fma2(u64 a, u64 b, u64 c) {
    u64 d; asm("fma.rn.f32x2 %0, %1, %2, %3;" : "=l"(d) : "l"(a), "l"(b), "l"(c)); return d;
}
__device__ __forceinline__ u64 pack2(float lo, float hi) {
    u64 d; asm("mov.b64 %0, {%1, %2};" : "=l"(d) : "f"(lo), "f"(hi)); return d;
}
__device__ __forceinline__ void unpack2(u64 v, float& lo, float& hi) {
    asm("mov.b64 {%0, %1}, %2;" : "=f"(lo), "=f"(hi) : "l"(v));
}
__device__ __forceinline__ float fsigmoid(float x) {
    return __fdividef(1.f, 1.f + __expf(-x));
}
__device__ __forceinline__ float ftanh(float x) {
    float e = __expf(-2.f * x);
    return __fdividef(1.f - e, 1.f + e);
}

// -------- device scratch --------
__device__ __align__(128) float g_msg[(size_t)N_EDGES * HID];   // 256 MB (CSR-ordered)
__device__ __align__(128) float g_agg[(size_t)N_NODES * HID];   // 25.6 MB
__device__ __align__(128) int g_count[N_NODES];
__device__ __align__(128) int g_rowstart[N_NODES + 1];
__device__ __align__(128) int g_cursor[N_NODES];
__device__ __align__(128) int g_src[N_EDGES];
__device__ __align__(128) int g_eperm[N_EDGES];

// -------- CSR build: histogram --------
__global__ __launch_bounds__(256) void hist_kernel(const int* __restrict__ eidx) {
    int t = blockIdx.x * 256 + threadIdx.x;
    if (t >= N_EDGES) return;
    int dst = eidx[t];
    if ((unsigned)dst < N_NODES) atomicAdd(&g_count[dst], 1);
}

// -------- CSR build: exclusive scan (single block) --------
__global__ __launch_bounds__(1024) void scan_kernel() {
    __shared__ int s[1024];
    const int T = 1024;
    const int tid = threadIdx.x;
    const int chunk = (N_NODES + T - 1) / T;
    const int start = tid * chunk;
    int sum = 0;
    for (int i = 0; i < chunk; ++i) {
        int idx = start + i;
        if (idx < N_NODES) sum += g_count[idx];
    }
    s[tid] = sum;
    __syncthreads();
    for (int off = 1; off < T; off <<= 1) {
        int v = 0;
        if (tid >= off) v = s[tid - off];
        __syncthreads();
        if (tid >= off) s[tid] += v;
        __syncthreads();
    }
    int run = (tid == 0) ? 0 : s[tid - 1];
    for (int i = 0; i < chunk; ++i) {
        int idx = start + i;
        if (idx < N_NODES) {
            g_rowstart[idx] = run;
            g_cursor[idx]   = run;
            run += g_count[idx];
        }
    }
    if (tid == T - 1) g_rowstart[N_NODES] = run;
}

// -------- CSR build: bucket placement --------
__global__ __launch_bounds__(256) void place_kernel(const int* __restrict__ eidx) {
    int t = blockIdx.x * 256 + threadIdx.x;
    if (t >= N_EDGES) return;
    int dst = eidx[t];
    int src = eidx[N_EDGES + t];
    if ((unsigned)dst >= N_NODES || (unsigned)src >= N_NODES) { g_eperm[t] = 0; return; }
    int pos = atomicAdd(&g_cursor[dst], 1);
    g_src[pos] = src;
    g_eperm[t] = pos;
}

// -------- K1: msg MLP as register-tiled GEMM (4 edges x 8 outputs per thread) --
// CTA = 256 threads, 128-edge tile. ex = tid&31 (edge group of 4), oy = tid>>5
// (output group of 8). Activations staged transposed [k][edge] (pitch 132,
// conflict-free LDS.128); weights transposed [k][out] so f32x2 operands load
// directly as u64 (warp-uniform broadcast). LDS:FFMA2 = 3:16.
#define ET 128
#define EPAD 132
#define MSG_SMEM_FLOATS ((EDIM + HID) * EPAD + EDIM * HID + HID * HID)
#define MSG_SMEM_BYTES  (MSG_SMEM_FLOATS * 4)

__global__ __launch_bounds__(256) void msg_kernel(
    const float* __restrict__ ea,
    const float* __restrict__ W1, const float* __restrict__ b1,
    const float* __restrict__ W2, const float* __restrict__ b2)
{
    extern __shared__ float sm[];
    float* attrT = sm;                   // [32][EPAD]
    float* hidT  = attrT + EDIM * EPAD;  // [64][EPAD]
    float* sW1   = hidT + HID * EPAD;    // [k][h]
    float* sW2   = sW1 + EDIM * HID;     // [k2][d]

    const int tid = threadIdx.x;
    const int ex = tid & 31;
    const int oy = tid >> 5;
    const int eb = blockIdx.x * ET;

    // stage + transpose weights
    for (int i = tid; i < EDIM * HID; i += 256) {
        int k = i >> 6, h = i & 63;
        sW1[i] = W1[h * EDIM + k];
    }
    for (int i = tid; i < HID * HID; i += 256) {
        int k = i >> 6, d = i & 63;
        sW2[i] = W2[d * HID + k];
    }
    // stage + transpose edge_attr (float4 gmem loads, coalesced)
    const float4* ea4 = reinterpret_cast<const float4*>(ea);
    for (int i = tid; i < ET * 8; i += 256) {
        int e = i >> 3, k4 = i & 7;
        long long ge = (long long)eb + e;
        float4 v = (ge < N_EDGES) ? __ldg(&ea4[ge * 8 + k4]) : make_float4(0.f, 0.f, 0.f, 0.f);
        attrT[(4 * k4 + 0) * EPAD + e] = v.x;
        attrT[(4 * k4 + 1) * EPAD + e] = v.y;
        attrT[(4 * k4 + 2) * EPAD + e] = v.z;
        attrT[(4 * k4 + 3) * EPAD + e] = v.w;
    }
    __syncthreads();

    // ---- layer 1: acc[e*4+hp] covers edge eb+ex*4+e, h = oy*8+2hp(+half) ----
    u64 acc[16];
    {
        const u64* b1p = reinterpret_cast<const u64*>(b1);
        #pragma unroll
        for (int hp = 0; hp < 4; ++hp) {
            u64 b = __ldg(&b1p[oy * 4 + hp]);
            acc[hp] = acc[4 + hp] = acc[8 + hp] = acc[12 + hp] = b;
        }
        #pragma unroll 2
        for (int k = 0; k < EDIM; ++k) {
            float4 a = *reinterpret_cast<const float4*>(&attrT[k * EPAD + ex * 4]);
            const u64* wp = reinterpret_cast<const u64*>(&sW1[k * HID + oy * 8]);
            u64 w0 = wp[0], w1 = wp[1], w2 = wp[2], w3 = wp[3];
            u64 a0 = pack2(a.x, a.x), a1 = pack2(a.y, a.y);
            u64 a2 = pack2(a.z, a.z), a3 = pack2(a.w, a.w);
            acc[0]  = fma2(a0, w0, acc[0]);  acc[1]  = fma2(a0, w1, acc[1]);
            acc[2]  = fma2(a0, w2, acc[2]);  acc[3]  = fma2(a0, w3, acc[3]);
            acc[4]  = fma2(a1, w0, acc[4]);  acc[5]  = fma2(a1, w1, acc[5]);
            acc[6]  = fma2(a1, w2, acc[6]);  acc[7]  = fma2(a1, w3, acc[7]);
            acc[8]  = fma2(a2, w0, acc[8]);  acc[9]  = fma2(a2, w1, acc[9]);
            acc[10] = fma2(a2, w2, acc[10]); acc[11] = fma2(a2, w3, acc[11]);
            acc[12] = fma2(a3, w0, acc[12]); acc[13] = fma2(a3, w1, acc[13]);
            acc[14] = fma2(a3, w2, acc[14]); acc[15] = fma2(a3, w3, acc[15]);
        }
        // relu + write hidT[h][edge] via STS.128 (conflict-free)
        #pragma unroll
        for (int hp = 0; hp < 4; ++hp) {
            float l0, u0, l1, u1, l2, u2, l3, u3;
            unpack2(acc[hp],      l0, u0);
            unpack2(acc[4 + hp],  l1, u1);
            unpack2(acc[8 + hp],  l2, u2);
            unpack2(acc[12 + hp], l3, u3);
            float4 vlo = make_float4(fmaxf(l0, 0.f), fmaxf(l1, 0.f), fmaxf(l2, 0.f), fmaxf(l3, 0.f));
            float4 vhi = make_float4(fmaxf(u0, 0.f), fmaxf(u1, 0.f), fmaxf(u2, 0.f), fmaxf(u3, 0.f));
            int h = oy * 8 + 2 * hp;
            *reinterpret_cast<float4*>(&hidT[h * EPAD + ex * 4])       = vlo;
            *reinterpret_cast<float4*>(&hidT[(h + 1) * EPAD + ex * 4]) = vhi;
        }
    }
    __syncthreads();

    // ---- layer 2: same tile shape over k2 = 64 ----
    {
        const u64* b2p = reinterpret_cast<const u64*>(b2);
        #pragma unroll
        for (int op = 0; op < 4; ++op) {
            u64 b = __ldg(&b2p[oy * 4 + op]);
            acc[op] = acc[4 + op] = acc[8 + op] = acc[12 + op] = b;
        }
        #pragma unroll 2
        for (int k2 = 0; k2 < HID; ++k2) {
            float4 a = *reinterpret_cast<const float4*>(&hidT[k2 * EPAD + ex * 4]);
            const u64* wp = reinterpret_cast<const u64*>(&sW2[k2 * HID + oy * 8]);
            u64 w0 = wp[0], w1 = wp[1], w2 = wp[2], w3 = wp[3];
            u64 a0 = pack2(a.x, a.x), a1 = pack2(a.y, a.y);
            u64 a2 = pack2(a.z, a.z), a3 = pack2(a.w, a.w);
            acc[0]  = fma2(a0, w0, acc[0]);  acc[1]  = fma2(a0, w1, acc[1]);
            acc[2]  = fma2(a0, w2, acc[2]);  acc[3]  = fma2(a0, w3, acc[3]);
            acc[4]  = fma2(a1, w0, acc[4]);  acc[5]  = fma2(a1, w1, acc[5]);
            acc[6]  = fma2(a1, w2, acc[6]);  acc[7]  = fma2(a1, w3, acc[7]);
            acc[8]  = fma2(a2, w0, acc[8]);  acc[9]  = fma2(a2, w1, acc[9]);
            acc[10] = fma2(a2, w2, acc[10]); acc[11] = fma2(a2, w3, acc[11]);
            acc[12] = fma2(a3, w0, acc[12]); acc[13] = fma2(a3, w1, acc[13]);
            acc[14] = fma2(a3, w2, acc[14]); acc[15] = fma2(a3, w3, acc[15]);
        }
        // store: edge row g_msg[slot][oy*8 .. oy*8+7]
        #pragma unroll
        for (int e = 0; e < 4; ++e) {
            int ge = eb + ex * 4 + e;
            if (ge < N_EDGES) {
                int slot = g_eperm[ge];
                ulonglong2* op = reinterpret_cast<ulonglong2*>(&g_msg[(size_t)slot * HID + oy * 8]);
                op[0] = make_ulonglong2(acc[e * 4 + 0], acc[e * 4 + 1]);
                op[1] = make_ulonglong2(acc[e * 4 + 2], acc[e * 4 + 3]);
            }
        }
    }
}

// -------- K2: gather aggregation (no atomics) --------
__global__ __launch_bounds__(256) void gather_kernel(const float* __restrict__ h) {
    int t = blockIdx.x * 256 + threadIdx.x;
    int n = t >> 4;
    int q = t & 15;
    if (n >= N_NODES) return;
    int p  = g_rowstart[n];
    int re = g_rowstart[n + 1];
    float4 acc = make_float4(0.f, 0.f, 0.f, 0.f);
    for (; p + 1 < re; p += 2) {
        float4 m0 = *reinterpret_cast<const float4*>(&g_msg[(size_t)p * HID + q * 4]);
        float4 m1 = *reinterpret_cast<const float4*>(&g_msg[(size_t)(p + 1) * HID + q * 4]);
        int s0 = __ldg(&g_src[p]);
        int s1 = __ldg(&g_src[p + 1]);
        float4 h0 = __ldg(reinterpret_cast<const float4*>(&h[(size_t)s0 * HID + q * 4]));
        float4 h1 = __ldg(reinterpret_cast<const float4*>(&h[(size_t)s1 * HID + q * 4]));
        acc.x += m0.x * h0.x; acc.y += m0.y * h0.y; acc.z += m0.z * h0.z; acc.w += m0.w * h0.w;
        acc.x += m1.x * h1.x; acc.y += m1.y * h1.y; acc.z += m1.z * h1.z; acc.w += m1.w * h1.w;
    }
    if (p < re) {
        float4 m = *reinterpret_cast<const float4*>(&g_msg[(size_t)p * HID + q * 4]);
        int s = __ldg(&g_src[p]);
        float4 hv = __ldg(reinterpret_cast<const float4*>(&h[(size_t)s * HID + q * 4]));
        acc.x += m.x * hv.x; acc.y += m.y * hv.y; acc.z += m.z * hv.z; acc.w += m.w * hv.w;
    }
    *reinterpret_cast<float4*>(&g_agg[(size_t)n * HID + q * 4]) = acc;
}

// -------- K3: GRU via f32x2, node-pair accumulators, transposed data tiles ----
#define WPAD 67
#define DPAD 68
#define GRU_TILE 64
#define GRU_SMEM_FLOATS (2 * 192 * WPAD + 2 * GRU_TILE * DPAD)
#define GRU_SMEM_BYTES  (GRU_SMEM_FLOATS * 4)

__global__ __launch_bounds__(512) void gru_kernel(
    const float* __restrict__ Wih, const float* __restrict__ bih,
    const float* __restrict__ Whh, const float* __restrict__ bhh,
    float* __restrict__ h)
{
    extern __shared__ float sm[];
    float* sWih  = sm;                        // [192][WPAD]
    float* sWhh  = sWih + 192 * WPAD;
    float* sAggT = sWhh + 192 * WPAD;         // [64][DPAD]
    float* sHT   = sAggT + GRU_TILE * DPAD;

    const int tid = threadIdx.x;
    const int d = tid & 63;
    const int g = tid >> 6;

    for (int i = tid; i < 192 * 64; i += 512) {
        int r = i >> 6, c = i & 63;
        sWih[r * WPAD + c] = Wih[i];
        sWhh[r * WPAD + c] = Whh[i];
    }
    const float bi_r = __ldg(&bih[d]), bi_z = __ldg(&bih[64 + d]), bi_n = __ldg(&bih[128 + d]);
    const float bh_r = __ldg(&bhh[d]), bh_z = __ldg(&bhh[64 + d]), bh_n = __ldg(&bhh[128 + d]);
    const u64 brz2 = pack2(bi_r + bh_r, bi_r + bh_r);
    const u64 bzz2 = pack2(bi_z + bh_z, bi_z + bh_z);
    const u64 bin2 = pack2(bi_n, bi_n);
    const u64 bhn2 = pack2(bh_n, bh_n);
    __syncthreads();

    const int ntiles = (N_NODES + GRU_TILE - 1) / GRU_TILE;
    for (int tile = blockIdx.x; tile < ntiles; tile += gridDim.x) {
        const int nb = tile * GRU_TILE;
        for (int i = tid; i < GRU_TILE * 64; i += 512) {
            int node = i >> 6, k = i & 63;
            bool ok = (nb + node) < N_NODES;
            size_t gi = (size_t)(nb + node) * 64 + k;
            sAggT[k * DPAD + node] = ok ? g_agg[gi] : 0.f;
            sHT[k * DPAD + node]   = ok ? h[gi] : 0.f;
        }
        __syncthreads();

        u64 acc_r[4], acc_z[4], acc_in[4], acc_hn[4];
        #pragma unroll
        for (int jp = 0; jp < 4; ++jp) {
            acc_r[jp] = brz2; acc_z[jp] = bzz2; acc_in[jp] = bin2; acc_hn[jp] = bhn2;
        }

        #pragma unroll 2
        for (int k = 0; k < 64; ++k) {
            float wir = sWih[d * WPAD + k];
            float wiz = sWih[(64 + d) * WPAD + k];
            float win = sWih[(128 + d) * WPAD + k];
            float whr = sWhh[d * WPAD + k];
            float whz = sWhh[(64 + d) * WPAD + k];
            float whn = sWhh[(128 + d) * WPAD + k];
            u64 wir2 = pack2(wir, wir), wiz2 = pack2(wiz, wiz), win2 = pack2(win, win);
            u64 whr2 = pack2(whr, whr), whz2 = pack2(whz, whz), whn2 = pack2(whn, whn);
            const ulonglong2* aT = reinterpret_cast<const ulonglong2*>(&sAggT[k * DPAD + g * 8]);
            const ulonglong2* hT = reinterpret_cast<const ulonglong2*>(&sHT[k * DPAD + g * 8]);
            #pragma unroll
            for (int jq = 0; jq < 2; ++jq) {
                ulonglong2 aa = aT[jq];
                ulonglong2 hh = hT[jq];
                acc_r[2*jq]   = fma2(wir2, aa.x, acc_r[2*jq]);
                acc_r[2*jq]   = fma2(whr2, hh.x, acc_r[2*jq]);
                acc_z[2*jq]   = fma2(wiz2, aa.x, acc_z[2*jq]);
                acc_z[2*jq]   = fma2(whz2, hh.x, acc_z[2*jq]);
                acc_in[2*jq]  = fma2(win2, aa.x, acc_in[2*jq]);
                acc_hn[2*jq]  = fma2(whn2, hh.x, acc_hn[2*jq]);
                acc_r[2*jq+1] = fma2(wir2, aa.y, acc_r[2*jq+1]);
                acc_r[2*jq+1] = fma2(whr2, hh.y, acc_r[2*jq+1]);
                acc_z[2*jq+1] = fma2(wiz2, aa.y, acc_z[2*jq+1]);
                acc_z[2*jq+1] = fma2(whz2, hh.y, acc_z[2*jq+1]);
                acc_in[2*jq+1]= fma2(win2, aa.y, acc_in[2*jq+1]);
                acc_hn[2*jq+1]= fma2(whn2, hh.y, acc_hn[2*jq+1]);
            }
        }

        #pragma unroll
        for (int jp = 0; jp < 4; ++jp) {
            float r0, r1, z0, z1, n0, n1, hn0, hn1;
            unpack2(acc_r[jp], r0, r1);
            unpack2(acc_z[jp], z0, z1);
            unpack2(acc_in[jp], n0, n1);
            unpack2(acc_hn[jp], hn0, hn1);
            int na = g * 8 + 2 * jp;
            #pragma unroll
            for (int half = 0; half < 2; ++half) {
                int n = na + half;
                if (nb + n < N_NODES) {
                    float rv  = fsigmoid(half ? r1 : r0);
                    float zv  = fsigmoid(half ? z1 : z0);
                    float nnv = ftanh((half ? n1 : n0) + rv * (half ? hn1 : hn0));
                    float hp  = sHT[d * DPAD + n];
                    h[(size_t)(nb + n) * 64 + d] = (1.f - zv) * nnv + zv * hp;
                }
            }
        }
        __syncthreads();
    }
}

// -------- launch --------
extern "C" void kernel_launch(void* const* d_in, const int* in_sizes, int n_in,
                              void* d_out, int out_size)
{
    const float* h0   = (const float*)d_in[0];
    const float* ea   = (const float*)d_in[1];
    const int*   eidx = (const int*)d_in[2];     // int64 inputs arrive as int32
    const float* W1   = (const float*)d_in[3];
    const float* b1   = (const float*)d_in[4];
    const float* W2   = (const float*)d_in[5];
    const float* b2   = (const float*)d_in[6];
    const float* Wih  = (const float*)d_in[7];
    const float* bih  = (const float*)d_in[8];
    const float* Whh  = (const float*)d_in[9];
    const float* bhh  = (const float*)d_in[10];
    float* h = (float*)d_out;

    cudaFuncSetAttribute(gru_kernel, cudaFuncAttributeMaxDynamicSharedMemorySize,
                         GRU_SMEM_BYTES);
    cudaFuncSetAttribute(msg_kernel, cudaFuncAttributeMaxDynamicSharedMemorySize,
                         MSG_SMEM_BYTES);

    void* countPtr = nullptr;
    cudaGetSymbolAddress(&countPtr, g_count);

    cudaMemcpyAsync(h, h0, (size_t)N_NODES * HID * sizeof(float),
                    cudaMemcpyDeviceToDevice, 0);

    // CSR build (edge_index is launch-invariant)
    cudaMemsetAsync(countPtr, 0, N_NODES * sizeof(int), 0);
    hist_kernel<<<(N_EDGES + 255) / 256, 256>>>(eidx);
    scan_kernel<<<1, 1024>>>();
    place_kernel<<<(N_EDGES + 255) / 256, 256>>>(eidx);

    // launch slot 6 -> ncu (-s 5 -c 1) captures msg_kernel
    msg_kernel<<<(N_EDGES + ET - 1) / ET, 256, MSG_SMEM_BYTES>>>(ea, W1, b1, W2, b2);

    for (int s = 0; s < NSTEPS; ++s) {
        gather_kernel<<<(N_NODES * 16 + 255) / 256, 256>>>(h);
        gru_kernel<<<152, 512, GRU_SMEM_BYTES>>>(Wih, bih, Whh, bhh, h);
    }
}

// round 8
// speedup vs baseline: 1.6570x; 1.0527x over previous
#include <cuda_runtime.h>
#include <math.h>

#define N_NODES 100000
#define N_EDGES 1000000
#define HID 64
#define EDIM 32
#define NSTEPS 4

typedef unsigned long long u64;

// ---- packed f32x2 helpers (FFMA2: only reachable via PTX fma.rn.f32x2) ----
__device__ __forceinline__ u64 fma2(u64 a, u64 b, u64 c) {
    u64 d; asm("fma.rn.f32x2 %0, %1, %2, %3;" : "=l"(d) : "l"(a), "l"(b), "l"(c)); return d;
}
__device__ __forceinline__ u64 pack2(float lo, float hi) {
    u64 d; asm("mov.b64 %0, {%1, %2};" : "=l"(d) : "f"(lo), "f"(hi)); return d;
}
__device__ __forceinline__ void unpack2(u64 v, float& lo, float& hi) {
    asm("mov.b64 {%0, %1}, %2;" : "=f"(lo), "=f"(hi) : "l"(v));
}
__device__ __forceinline__ float fsigmoid(float x) {
    return __fdividef(1.f, 1.f + __expf(-x));
}
__device__ __forceinline__ float ftanh(float x) {
    float e = __expf(-2.f * x);
    return __fdividef(1.f - e, 1.f + e);
}

// -------- device scratch --------
__device__ __align__(128) float g_msg[(size_t)N_EDGES * HID];   // 256 MB (CSR-ordered)
__device__ __align__(128) float g_agg[(size_t)N_NODES * HID];   // 25.6 MB
__device__ __align__(128) float g_W1t[EDIM * HID];              // [k][h]
__device__ __align__(128) float g_W2t[HID * HID];               // [k2][d]
__device__ __align__(128) int g_count[N_NODES];
__device__ __align__(128) int g_rowstart[N_NODES + 1];
__device__ __align__(128) int g_cursor[N_NODES];
__device__ __align__(128) int g_src[N_EDGES];
__device__ __align__(128) int g_eperm[N_EDGES];

// -------- CSR build: histogram --------
__global__ __launch_bounds__(256) void hist_kernel(const int* __restrict__ eidx) {
    int t = blockIdx.x * 256 + threadIdx.x;
    if (t >= N_EDGES) return;
    int dst = eidx[t];
    if ((unsigned)dst < N_NODES) atomicAdd(&g_count[dst], 1);
}

// -------- CSR build: exclusive scan; ALSO transposes MLP weights (folded so
// msg_kernel stays at ncu launch slot 6) --------
__global__ __launch_bounds__(1024) void scan_kernel(
    const float* __restrict__ W1, const float* __restrict__ W2)
{
    // weight transpose (6144 elements, trivially absorbed)
    for (int i = threadIdx.x; i < EDIM * HID; i += 1024) {
        int k = i >> 6, h = i & 63;
        g_W1t[i] = W1[h * EDIM + k];
    }
    for (int i = threadIdx.x; i < HID * HID; i += 1024) {
        int k = i >> 6, d = i & 63;
        g_W2t[i] = W2[d * HID + k];
    }

    __shared__ int s[1024];
    const int T = 1024;
    const int tid = threadIdx.x;
    const int chunk = (N_NODES + T - 1) / T;
    const int start = tid * chunk;
    int sum = 0;
    for (int i = 0; i < chunk; ++i) {
        int idx = start + i;
        if (idx < N_NODES) sum += g_count[idx];
    }
    s[tid] = sum;
    __syncthreads();
    for (int off = 1; off < T; off <<= 1) {
        int v = 0;
        if (tid >= off) v = s[tid - off];
        __syncthreads();
        if (tid >= off) s[tid] += v;
        __syncthreads();
    }
    int run = (tid == 0) ? 0 : s[tid - 1];
    for (int i = 0; i < chunk; ++i) {
        int idx = start + i;
        if (idx < N_NODES) {
            g_rowstart[idx] = run;
            g_cursor[idx]   = run;
            run += g_count[idx];
        }
    }
    if (tid == T - 1) g_rowstart[N_NODES] = run;
}

// -------- CSR build: bucket placement --------
__global__ __launch_bounds__(256) void place_kernel(const int* __restrict__ eidx) {
    int t = blockIdx.x * 256 + threadIdx.x;
    if (t >= N_EDGES) return;
    int dst = eidx[t];
    int src = eidx[N_EDGES + t];
    if ((unsigned)dst >= N_NODES || (unsigned)src >= N_NODES) { g_eperm[t] = 0; return; }
    int pos = atomicAdd(&g_cursor[dst], 1);
    g_src[pos] = src;
    g_eperm[t] = pos;
}

// -------- K1: msg MLP, register tile 4 edges x 16 outputs (32 u64 acc) -------
// CTA = 256 threads, 256-edge tile. ex = tid&63 (edge quad), oy = tid>>6
// (16-output group). Per k: 1 LDS.128 act + 4 LDS.128 weights (ulonglong2,
// warp-uniform broadcast) feeding 32 FFMA2 -> 8 wavefronts / 32 FFMA2.
#define ET 256
#define EPAD 260
#define MSG_SMEM_FLOATS ((EDIM + HID) * EPAD + EDIM * HID + HID * HID)
#define MSG_SMEM_BYTES  (MSG_SMEM_FLOATS * 4)   // 124,416 B -> 1 CTA/SM

__global__ __launch_bounds__(256) void msg_kernel(
    const float* __restrict__ ea,
    const float* __restrict__ b1, const float* __restrict__ b2)
{
    extern __shared__ float sm[];
    float* attrT = sm;                   // [32][EPAD]
    float* hidT  = attrT + EDIM * EPAD;  // [64][EPAD]
    float* sW1   = hidT + HID * EPAD;    // [k][h]   32x64
    float* sW2   = sW1 + EDIM * HID;     // [k2][d]  64x64

    const int tid = threadIdx.x;
    const int ex = tid & 63;
    const int oy = tid >> 6;             // 0..3
    const int eb = blockIdx.x * ET;

    // stage pre-transposed weights linearly (coalesced float4)
    {
        const float4* w1p = reinterpret_cast<const float4*>(g_W1t);
        const float4* w2p = reinterpret_cast<const float4*>(g_W2t);
        float4* s1 = reinterpret_cast<float4*>(sW1);
        float4* s2 = reinterpret_cast<float4*>(sW2);
        for (int i = tid; i < (EDIM * HID) / 4; i += 256) s1[i] = w1p[i];
        for (int i = tid; i < (HID * HID) / 4; i += 256)  s2[i] = w2p[i];
    }
    // stage + transpose edge_attr (coalesced float4 gmem loads)
    const float4* ea4 = reinterpret_cast<const float4*>(ea);
    for (int i = tid; i < ET * 8; i += 256) {
        int e = i >> 3, k4 = i & 7;
        long long ge = (long long)eb + e;
        float4 v = (ge < N_EDGES) ? __ldg(&ea4[ge * 8 + k4]) : make_float4(0.f, 0.f, 0.f, 0.f);
        attrT[(4 * k4 + 0) * EPAD + e] = v.x;
        attrT[(4 * k4 + 1) * EPAD + e] = v.y;
        attrT[(4 * k4 + 2) * EPAD + e] = v.z;
        attrT[(4 * k4 + 3) * EPAD + e] = v.w;
    }
    __syncthreads();

    u64 acc[32];   // acc[e*8+hp]: edge eb+ex*4+e, outputs oy*16+2hp(+half)

    // ---- layer 1 ----
    {
        const u64* b1p = reinterpret_cast<const u64*>(b1);
        #pragma unroll
        for (int hp = 0; hp < 8; ++hp) {
            u64 b = __ldg(&b1p[oy * 8 + hp]);
            acc[hp] = acc[8 + hp] = acc[16 + hp] = acc[24 + hp] = b;
        }
        #pragma unroll 2
        for (int k = 0; k < EDIM; ++k) {
            float4 a = *reinterpret_cast<const float4*>(&attrT[k * EPAD + ex * 4]);
            const ulonglong2* wp = reinterpret_cast<const ulonglong2*>(&sW1[k * HID + oy * 16]);
            ulonglong2 wA = wp[0], wB = wp[1], wC = wp[2], wD = wp[3];
            u64 w[8] = {wA.x, wA.y, wB.x, wB.y, wC.x, wC.y, wD.x, wD.y};
            u64 a0 = pack2(a.x, a.x), a1 = pack2(a.y, a.y);
            u64 a2 = pack2(a.z, a.z), a3 = pack2(a.w, a.w);
            #pragma unroll
            for (int hp = 0; hp < 8; ++hp) {
                acc[hp]      = fma2(a0, w[hp], acc[hp]);
                acc[8 + hp]  = fma2(a1, w[hp], acc[8 + hp]);
                acc[16 + hp] = fma2(a2, w[hp], acc[16 + hp]);
                acc[24 + hp] = fma2(a3, w[hp], acc[24 + hp]);
            }
        }
        // relu + store hidT[h][edge] (STS.128, conflict-free)
        #pragma unroll
        for (int hp = 0; hp < 8; ++hp) {
            float l0, u0, l1, u1, l2, u2, l3, u3;
            unpack2(acc[hp],      l0, u0);
            unpack2(acc[8 + hp],  l1, u1);
            unpack2(acc[16 + hp], l2, u2);
            unpack2(acc[24 + hp], l3, u3);
            float4 vlo = make_float4(fmaxf(l0, 0.f), fmaxf(l1, 0.f), fmaxf(l2, 0.f), fmaxf(l3, 0.f));
            float4 vhi = make_float4(fmaxf(u0, 0.f), fmaxf(u1, 0.f), fmaxf(u2, 0.f), fmaxf(u3, 0.f));
            int h = oy * 16 + 2 * hp;
            *reinterpret_cast<float4*>(&hidT[h * EPAD + ex * 4])       = vlo;
            *reinterpret_cast<float4*>(&hidT[(h + 1) * EPAD + ex * 4]) = vhi;
        }
    }
    __syncthreads();

    // ---- layer 2 ----
    {
        const u64* b2p = reinterpret_cast<const u64*>(b2);
        #pragma unroll
        for (int hp = 0; hp < 8; ++hp) {
            u64 b = __ldg(&b2p[oy * 8 + hp]);
            acc[hp] = acc[8 + hp] = acc[16 + hp] = acc[24 + hp] = b;
        }
        #pragma unroll 2
        for (int k2 = 0; k2 < HID; ++k2) {
            float4 a = *reinterpret_cast<const float4*>(&hidT[k2 * EPAD + ex * 4]);
            const ulonglong2* wp = reinterpret_cast<const ulonglong2*>(&sW2[k2 * HID + oy * 16]);
            ulonglong2 wA = wp[0], wB = wp[1], wC = wp[2], wD = wp[3];
            u64 w[8] = {wA.x, wA.y, wB.x, wB.y, wC.x, wC.y, wD.x, wD.y};
            u64 a0 = pack2(a.x, a.x), a1 = pack2(a.y, a.y);
            u64 a2 = pack2(a.z, a.z), a3 = pack2(a.w, a.w);
            #pragma unroll
            for (int hp = 0; hp < 8; ++hp) {
                acc[hp]      = fma2(a0, w[hp], acc[hp]);
                acc[8 + hp]  = fma2(a1, w[hp], acc[8 + hp]);
                acc[16 + hp] = fma2(a2, w[hp], acc[16 + hp]);
                acc[24 + hp] = fma2(a3, w[hp], acc[24 + hp]);
            }
        }
        // store: edge row g_msg[slot][oy*16 .. oy*16+15]
        #pragma unroll
        for (int e = 0; e < 4; ++e) {
            int ge = eb + ex * 4 + e;
            if (ge < N_EDGES) {
                int slot = g_eperm[ge];
                ulonglong2* op = reinterpret_cast<ulonglong2*>(&g_msg[(size_t)slot * HID + oy * 16]);
                op[0] = make_ulonglong2(acc[e * 8 + 0], acc[e * 8 + 1]);
                op[1] = make_ulonglong2(acc[e * 8 + 2], acc[e * 8 + 3]);
                op[2] = make_ulonglong2(acc[e * 8 + 4], acc[e * 8 + 5]);
                op[3] = make_ulonglong2(acc[e * 8 + 6], acc[e * 8 + 7]);
            }
        }
    }
}

// -------- K2: gather aggregation (no atomics; streaming reads of g_msg) ------
__global__ __launch_bounds__(256) void gather_kernel(const float* __restrict__ h) {
    int t = blockIdx.x * 256 + threadIdx.x;
    int n = t >> 4;
    int q = t & 15;
    if (n >= N_NODES) return;
    int p  = g_rowstart[n];
    int re = g_rowstart[n + 1];
    float4 acc = make_float4(0.f, 0.f, 0.f, 0.f);
    for (; p + 1 < re; p += 2) {
        float4 m0 = __ldcs(reinterpret_cast<const float4*>(&g_msg[(size_t)p * HID + q * 4]));
        float4 m1 = __ldcs(reinterpret_cast<const float4*>(&g_msg[(size_t)(p + 1) * HID + q * 4]));
        int s0 = __ldg(&g_src[p]);
        int s1 = __ldg(&g_src[p + 1]);
        float4 h0 = __ldg(reinterpret_cast<const float4*>(&h[(size_t)s0 * HID + q * 4]));
        float4 h1 = __ldg(reinterpret_cast<const float4*>(&h[(size_t)s1 * HID + q * 4]));
        acc.x += m0.x * h0.x; acc.y += m0.y * h0.y; acc.z += m0.z * h0.z; acc.w += m0.w * h0.w;
        acc.x += m1.x * h1.x; acc.y += m1.y * h1.y; acc.z += m1.z * h1.z; acc.w += m1.w * h1.w;
    }
    if (p < re) {
        float4 m = __ldcs(reinterpret_cast<const float4*>(&g_msg[(size_t)p * HID + q * 4]));
        int s = __ldg(&g_src[p]);
        float4 hv = __ldg(reinterpret_cast<const float4*>(&h[(size_t)s * HID + q * 4]));
        acc.x += m.x * hv.x; acc.y += m.y * hv.y; acc.z += m.z * hv.z; acc.w += m.w * hv.w;
    }
    *reinterpret_cast<float4*>(&g_agg[(size_t)n * HID + q * 4]) = acc;
}

// -------- K3: GRU via f32x2, node-pair accumulators, transposed data tiles ----
#define WPAD 67
#define DPAD 68
#define GRU_TILE 64
#define GRU_SMEM_FLOATS (2 * 192 * WPAD + 2 * GRU_TILE * DPAD)
#define GRU_SMEM_BYTES  (GRU_SMEM_FLOATS * 4)

__global__ __launch_bounds__(512) void gru_kernel(
    const float* __restrict__ Wih, const float* __restrict__ bih,
    const float* __restrict__ Whh, const float* __restrict__ bhh,
    float* __restrict__ h)
{
    extern __shared__ float sm[];
    float* sWih  = sm;                        // [192][WPAD]
    float* sWhh  = sWih + 192 * WPAD;
    float* sAggT = sWhh + 192 * WPAD;         // [64][DPAD]
    float* sHT   = sAggT + GRU_TILE * DPAD;

    const int tid = threadIdx.x;
    const int d = tid & 63;
    const int g = tid >> 6;

    for (int i = tid; i < 192 * 64; i += 512) {
        int r = i >> 6, c = i & 63;
        sWih[r * WPAD + c] = Wih[i];
        sWhh[r * WPAD + c] = Whh[i];
    }
    const float bi_r = __ldg(&bih[d]), bi_z = __ldg(&bih[64 + d]), bi_n = __ldg(&bih[128 + d]);
    const float bh_r = __ldg(&bhh[d]), bh_z = __ldg(&bhh[64 + d]), bh_n = __ldg(&bhh[128 + d]);
    const u64 brz2 = pack2(bi_r + bh_r, bi_r + bh_r);
    const u64 bzz2 = pack2(bi_z + bh_z, bi_z + bh_z);
    const u64 bin2 = pack2(bi_n, bi_n);
    const u64 bhn2 = pack2(bh_n, bh_n);
    __syncthreads();

    const int ntiles = (N_NODES + GRU_TILE - 1) / GRU_TILE;
    for (int tile = blockIdx.x; tile < ntiles; tile += gridDim.x) {
        const int nb = tile * GRU_TILE;
        for (int i = tid; i < GRU_TILE * 64; i += 512) {
            int node = i >> 6, k = i & 63;
            bool ok = (nb + node) < N_NODES;
            size_t gi = (size_t)(nb + node) * 64 + k;
            sAggT[k * DPAD + node] = ok ? g_agg[gi] : 0.f;
            sHT[k * DPAD + node]   = ok ? h[gi] : 0.f;
        }
        __syncthreads();

        u64 acc_r[4], acc_z[4], acc_in[4], acc_hn[4];
        #pragma unroll
        for (int jp = 0; jp < 4; ++jp) {
            acc_r[jp] = brz2; acc_z[jp] = bzz2; acc_in[jp] = bin2; acc_hn[jp] = bhn2;
        }

        #pragma unroll 2
        for (int k = 0; k < 64; ++k) {
            float wir = sWih[d * WPAD + k];
            float wiz = sWih[(64 + d) * WPAD + k];
            float win = sWih[(128 + d) * WPAD + k];
            float whr = sWhh[d * WPAD + k];
            float whz = sWhh[(64 + d) * WPAD + k];
            float whn = sWhh[(128 + d) * WPAD + k];
            u64 wir2 = pack2(wir, wir), wiz2 = pack2(wiz, wiz), win2 = pack2(win, win);
            u64 whr2 = pack2(whr, whr), whz2 = pack2(whz, whz), whn2 = pack2(whn, whn);
            const ulonglong2* aT = reinterpret_cast<const ulonglong2*>(&sAggT[k * DPAD + g * 8]);
            const ulonglong2* hT = reinterpret_cast<const ulonglong2*>(&sHT[k * DPAD + g * 8]);
            #pragma unroll
            for (int jq = 0; jq < 2; ++jq) {
                ulonglong2 aa = aT[jq];
                ulonglong2 hh = hT[jq];
                acc_r[2*jq]   = fma2(wir2, aa.x, acc_r[2*jq]);
                acc_r[2*jq]   = fma2(whr2, hh.x, acc_r[2*jq]);
                acc_z[2*jq]   = fma2(wiz2, aa.x, acc_z[2*jq]);
                acc_z[2*jq]   = fma2(whz2, hh.x, acc_z[2*jq]);
                acc_in[2*jq]  = fma2(win2, aa.x, acc_in[2*jq]);
                acc_hn[2*jq]  = fma2(whn2, hh.x, acc_hn[2*jq]);
                acc_r[2*jq+1] = fma2(wir2, aa.y, acc_r[2*jq+1]);
                acc_r[2*jq+1] = fma2(whr2, hh.y, acc_r[2*jq+1]);
                acc_z[2*jq+1] = fma2(wiz2, aa.y, acc_z[2*jq+1]);
                acc_z[2*jq+1] = fma2(whz2, hh.y, acc_z[2*jq+1]);
                acc_in[2*jq+1]= fma2(win2, aa.y, acc_in[2*jq+1]);
                acc_hn[2*jq+1]= fma2(whn2, hh.y, acc_hn[2*jq+1]);
            }
        }

        #pragma unroll
        for (int jp = 0; jp < 4; ++jp) {
            float r0, r1, z0, z1, n0, n1, hn0, hn1;
            unpack2(acc_r[jp], r0, r1);
            unpack2(acc_z[jp], z0, z1);
            unpack2(acc_in[jp], n0, n1);
            unpack2(acc_hn[jp], hn0, hn1);
            int na = g * 8 + 2 * jp;
            #pragma unroll
            for (int half = 0; half < 2; ++half) {
                int n = na + half;
                if (nb + n < N_NODES) {
                    float rv  = fsigmoid(half ? r1 : r0);
                    float zv  = fsigmoid(half ? z1 : z0);
                    float nnv = ftanh((half ? n1 : n0) + rv * (half ? hn1 : hn0));
                    float hp  = sHT[d * DPAD + n];
                    h[(size_t)(nb + n) * 64 + d] = (1.f - zv) * nnv + zv * hp;
                }
            }
        }
        __syncthreads();
    }
}

// -------- launch --------
extern "C" void kernel_launch(void* const* d_in, const int* in_sizes, int n_in,
                              void* d_out, int out_size)
{
    const float* h0   = (const float*)d_in[0];
    const float* ea   = (const float*)d_in[1];
    const int*   eidx = (const int*)d_in[2];     // int64 inputs arrive as int32
    const float* W1   = (const float*)d_in[3];
    const float* b1   = (const float*)d_in[4];
    const float* W2   = (const float*)d_in[5];
    const float* b2   = (const float*)d_in[6];
    const float* Wih  = (const float*)d_in[7];
    const float* bih  = (const float*)d_in[8];
    const float* Whh  = (const float*)d_in[9];
    const float* bhh  = (const float*)d_in[10];
    float* h = (float*)d_out;

    cudaFuncSetAttribute(gru_kernel, cudaFuncAttributeMaxDynamicSharedMemorySize,
                         GRU_SMEM_BYTES);
    cudaFuncSetAttribute(msg_kernel, cudaFuncAttributeMaxDynamicSharedMemorySize,
                         MSG_SMEM_BYTES);

    void* countPtr = nullptr;
    cudaGetSymbolAddress(&countPtr, g_count);

    cudaMemcpyAsync(h, h0, (size_t)N_NODES * HID * sizeof(float),
                    cudaMemcpyDeviceToDevice, 0);

    // CSR build (edge_index is launch-invariant); scan also transposes weights
    cudaMemsetAsync(countPtr, 0, N_NODES * sizeof(int), 0);
    hist_kernel<<<(N_EDGES + 255) / 256, 256>>>(eidx);
    scan_kernel<<<1, 1024>>>(W1, W2);
    place_kernel<<<(N_EDGES + 255) / 256, 256>>>(eidx);

    // launch slot 6 -> ncu (-s 5 -c 1) captures msg_kernel
    msg_kernel<<<(N_EDGES + ET - 1) / ET, 256, MSG_SMEM_BYTES>>>(ea, b1, b2);

    for (int s = 0; s < NSTEPS; ++s) {
        gather_kernel<<<(N_NODES * 16 + 255) / 256, 256>>>(h);
        gru_kernel<<<152, 512, GRU_SMEM_BYTES>>>(Wih, bih, Whh, bhh, h);
    }
}

// round 9
// speedup vs baseline: 1.8892x; 1.1401x over previous
#include <cuda_runtime.h>
#include <math.h>

#define N_NODES 100000
#define N_EDGES 1000000
#define HID 64
#define EDIM 32
#define NSTEPS 4

typedef unsigned long long u64;

// ---- packed f32x2 helpers (FFMA2: only reachable via PTX fma.rn.f32x2) ----
__device__ __forceinline__ u64 fma2(u64 a, u64 b, u64 c) {
    u64 d; asm("fma.rn.f32x2 %0, %1, %2, %3;" : "=l"(d) : "l"(a), "l"(b), "l"(c)); return d;
}
__device__ __forceinline__ u64 pack2(float lo, float hi) {
    u64 d; asm("mov.b64 %0, {%1, %2};" : "=l"(d) : "f"(lo), "f"(hi)); return d;
}
__device__ __forceinline__ void unpack2(u64 v, float& lo, float& hi) {
    asm("mov.b64 {%0, %1}, %2;" : "=f"(lo), "=f"(hi) : "l"(v));
}
__device__ __forceinline__ float fsigmoid(float x) {
    return __fdividef(1.f, 1.f + __expf(-x));
}
__device__ __forceinline__ float ftanh(float x) {
    float e = __expf(-2.f * x);
    return __fdividef(1.f - e, 1.f + e);
}

// -------- device scratch --------
__device__ __align__(128) float g_msg[(size_t)N_EDGES * HID];   // 256 MB (CSR-ordered)
__device__ __align__(128) float g_agg[(size_t)N_NODES * HID];   // 25.6 MB
__device__ __align__(128) float g_W1t[EDIM * HID];              // [k][h]
__device__ __align__(128) float g_W2t[HID * HID];               // [k2][d]
__device__ __align__(128) int g_count[N_NODES];
__device__ __align__(128) int g_rowstart[N_NODES + 1];
__device__ __align__(128) int g_cursor[N_NODES];
__device__ __align__(128) int g_src[N_EDGES];
__device__ __align__(128) int g_eperm[N_EDGES];

// -------- CSR build: histogram --------
__global__ __launch_bounds__(256) void hist_kernel(const int* __restrict__ eidx) {
    int t = blockIdx.x * 256 + threadIdx.x;
    if (t >= N_EDGES) return;
    int dst = eidx[t];
    if ((unsigned)dst < N_NODES) atomicAdd(&g_count[dst], 1);
}

// -------- CSR build: exclusive scan; also transposes MLP weights --------
__global__ __launch_bounds__(1024) void scan_kernel(
    const float* __restrict__ W1, const float* __restrict__ W2)
{
    for (int i = threadIdx.x; i < EDIM * HID; i += 1024) {
        int k = i >> 6, h = i & 63;
        g_W1t[i] = W1[h * EDIM + k];
    }
    for (int i = threadIdx.x; i < HID * HID; i += 1024) {
        int k = i >> 6, d = i & 63;
        g_W2t[i] = W2[d * HID + k];
    }

    __shared__ int s[1024];
    const int T = 1024;
    const int tid = threadIdx.x;
    const int chunk = (N_NODES + T - 1) / T;
    const int start = tid * chunk;
    int sum = 0;
    for (int i = 0; i < chunk; ++i) {
        int idx = start + i;
        if (idx < N_NODES) sum += g_count[idx];
    }
    s[tid] = sum;
    __syncthreads();
    for (int off = 1; off < T; off <<= 1) {
        int v = 0;
        if (tid >= off) v = s[tid - off];
        __syncthreads();
        if (tid >= off) s[tid] += v;
        __syncthreads();
    }
    int run = (tid == 0) ? 0 : s[tid - 1];
    for (int i = 0; i < chunk; ++i) {
        int idx = start + i;
        if (idx < N_NODES) {
            g_rowstart[idx] = run;
            g_cursor[idx]   = run;
            run += g_count[idx];
        }
    }
    if (tid == T - 1) g_rowstart[N_NODES] = run;
}

// -------- CSR build: bucket placement --------
__global__ __launch_bounds__(256) void place_kernel(const int* __restrict__ eidx) {
    int t = blockIdx.x * 256 + threadIdx.x;
    if (t >= N_EDGES) return;
    int dst = eidx[t];
    int src = eidx[N_EDGES + t];
    if ((unsigned)dst >= N_NODES || (unsigned)src >= N_NODES) { g_eperm[t] = 0; return; }
    int pos = atomicAdd(&g_cursor[dst], 1);
    g_src[pos] = src;
    g_eperm[t] = pos;
}

// -------- K1: msg MLP, 4 edges x 8 outputs per thread, 75 KB smem ------------
// ET=128 edge tile, 2 CTAs/SM (occupancy fix vs R8) + LDS.128 weight loads
// (vectorization fix vs R7). ex = lane (edge quad), oy = warp (8-output group).
// Per warp per k: 1 contiguous LDS.128 (act) + 2 broadcast LDS.128 (weights)
// feeding 16 FFMA2 -> fma-pipe bound at 16 warps/SM.
#define ET 128
#define EPAD 132
#define MSG_SMEM_FLOATS ((EDIM + HID) * EPAD + EDIM * HID + HID * HID)
#define MSG_SMEM_BYTES  (MSG_SMEM_FLOATS * 4)   // 75,264 B -> 2 CTAs/SM

__global__ __launch_bounds__(256, 2) void msg_kernel(
    const float* __restrict__ ea,
    const float* __restrict__ b1, const float* __restrict__ b2)
{
    extern __shared__ float sm[];
    float* attrT = sm;                   // [32][EPAD]
    float* hidT  = attrT + EDIM * EPAD;  // [64][EPAD]
    float* sW1   = hidT + HID * EPAD;    // [k][h]   32x64
    float* sW2   = sW1 + EDIM * HID;     // [k2][d]  64x64

    const int tid = threadIdx.x;
    const int ex = tid & 31;             // lane
    const int oy = tid >> 5;             // warp 0..7
    const int eb = blockIdx.x * ET;

    // stage pre-transposed weights linearly (coalesced float4)
    {
        const float4* w1p = reinterpret_cast<const float4*>(g_W1t);
        const float4* w2p = reinterpret_cast<const float4*>(g_W2t);
        float4* s1 = reinterpret_cast<float4*>(sW1);
        float4* s2 = reinterpret_cast<float4*>(sW2);
        for (int i = tid; i < (EDIM * HID) / 4; i += 256) s1[i] = w1p[i];
        for (int i = tid; i < (HID * HID) / 4; i += 256)  s2[i] = w2p[i];
    }
    // stage + transpose edge_attr (coalesced float4 gmem loads)
    const float4* ea4 = reinterpret_cast<const float4*>(ea);
    for (int i = tid; i < ET * 8; i += 256) {
        int e = i >> 3, k4 = i & 7;
        long long ge = (long long)eb + e;
        float4 v = (ge < N_EDGES) ? __ldg(&ea4[ge * 8 + k4]) : make_float4(0.f, 0.f, 0.f, 0.f);
        attrT[(4 * k4 + 0) * EPAD + e] = v.x;
        attrT[(4 * k4 + 1) * EPAD + e] = v.y;
        attrT[(4 * k4 + 2) * EPAD + e] = v.z;
        attrT[(4 * k4 + 3) * EPAD + e] = v.w;
    }
    __syncthreads();

    u64 acc[16];   // acc[e*4+hp]: edge eb+ex*4+e, outputs oy*8+2hp(+half)

    // ---- layer 1 ----
    {
        const u64* b1p = reinterpret_cast<const u64*>(b1);
        #pragma unroll
        for (int hp = 0; hp < 4; ++hp) {
            u64 b = __ldg(&b1p[oy * 4 + hp]);
            acc[hp] = acc[4 + hp] = acc[8 + hp] = acc[12 + hp] = b;
        }
        #pragma unroll 2
        for (int k = 0; k < EDIM; ++k) {
            float4 a = *reinterpret_cast<const float4*>(&attrT[k * EPAD + ex * 4]);
            const ulonglong2* wp = reinterpret_cast<const ulonglong2*>(&sW1[k * HID + oy * 8]);
            ulonglong2 wA = wp[0], wB = wp[1];
            u64 w0 = wA.x, w1 = wA.y, w2 = wB.x, w3 = wB.y;
            u64 a0 = pack2(a.x, a.x), a1 = pack2(a.y, a.y);
            u64 a2 = pack2(a.z, a.z), a3 = pack2(a.w, a.w);
            acc[0]  = fma2(a0, w0, acc[0]);  acc[1]  = fma2(a0, w1, acc[1]);
            acc[2]  = fma2(a0, w2, acc[2]);  acc[3]  = fma2(a0, w3, acc[3]);
            acc[4]  = fma2(a1, w0, acc[4]);  acc[5]  = fma2(a1, w1, acc[5]);
            acc[6]  = fma2(a1, w2, acc[6]);  acc[7]  = fma2(a1, w3, acc[7]);
            acc[8]  = fma2(a2, w0, acc[8]);  acc[9]  = fma2(a2, w1, acc[9]);
            acc[10] = fma2(a2, w2, acc[10]); acc[11] = fma2(a2, w3, acc[11]);
            acc[12] = fma2(a3, w0, acc[12]); acc[13] = fma2(a3, w1, acc[13]);
            acc[14] = fma2(a3, w2, acc[14]); acc[15] = fma2(a3, w3, acc[15]);
        }
        // relu + store hidT[h][edge] (STS.128, conflict-free)
        #pragma unroll
        for (int hp = 0; hp < 4; ++hp) {
            float l0, u0, l1, u1, l2, u2, l3, u3;
            unpack2(acc[hp],      l0, u0);
            unpack2(acc[4 + hp],  l1, u1);
            unpack2(acc[8 + hp],  l2, u2);
            unpack2(acc[12 + hp], l3, u3);
            float4 vlo = make_float4(fmaxf(l0, 0.f), fmaxf(l1, 0.f), fmaxf(l2, 0.f), fmaxf(l3, 0.f));
            float4 vhi = make_float4(fmaxf(u0, 0.f), fmaxf(u1, 0.f), fmaxf(u2, 0.f), fmaxf(u3, 0.f));
            int h = oy * 8 + 2 * hp;
            *reinterpret_cast<float4*>(&hidT[h * EPAD + ex * 4])       = vlo;
            *reinterpret_cast<float4*>(&hidT[(h + 1) * EPAD + ex * 4]) = vhi;
        }
    }
    __syncthreads();

    // ---- layer 2 ----
    {
        const u64* b2p = reinterpret_cast<const u64*>(b2);
        #pragma unroll
        for (int hp = 0; hp < 4; ++hp) {
            u64 b = __ldg(&b2p[oy * 4 + hp]);
            acc[hp] = acc[4 + hp] = acc[8 + hp] = acc[12 + hp] = b;
        }
        #pragma unroll 2
        for (int k2 = 0; k2 < HID; ++k2) {
            float4 a = *reinterpret_cast<const float4*>(&hidT[k2 * EPAD + ex * 4]);
            const ulonglong2* wp = reinterpret_cast<const ulonglong2*>(&sW2[k2 * HID + oy * 8]);
            ulonglong2 wA = wp[0], wB = wp[1];
            u64 w0 = wA.x, w1 = wA.y, w2 = wB.x, w3 = wB.y;
            u64 a0 = pack2(a.x, a.x), a1 = pack2(a.y, a.y);
            u64 a2 = pack2(a.z, a.z), a3 = pack2(a.w, a.w);
            acc[0]  = fma2(a0, w0, acc[0]);  acc[1]  = fma2(a0, w1, acc[1]);
            acc[2]  = fma2(a0, w2, acc[2]);  acc[3]  = fma2(a0, w3, acc[3]);
            acc[4]  = fma2(a1, w0, acc[4]);  acc[5]  = fma2(a1, w1, acc[5]);
            acc[6]  = fma2(a1, w2, acc[6]);  acc[7]  = fma2(a1, w3, acc[7]);
            acc[8]  = fma2(a2, w0, acc[8]);  acc[9]  = fma2(a2, w1, acc[9]);
            acc[10] = fma2(a2, w2, acc[10]); acc[11] = fma2(a2, w3, acc[11]);
            acc[12] = fma2(a3, w0, acc[12]); acc[13] = fma2(a3, w1, acc[13]);
            acc[14] = fma2(a3, w2, acc[14]); acc[15] = fma2(a3, w3, acc[15]);
        }
        // store: edge row g_msg[slot][oy*8 .. oy*8+7]
        #pragma unroll
        for (int e = 0; e < 4; ++e) {
            int ge = eb + ex * 4 + e;
            if (ge < N_EDGES) {
                int slot = g_eperm[ge];
                ulonglong2* op = reinterpret_cast<ulonglong2*>(&g_msg[(size_t)slot * HID + oy * 8]);
                op[0] = make_ulonglong2(acc[e * 4 + 0], acc[e * 4 + 1]);
                op[1] = make_ulonglong2(acc[e * 4 + 2], acc[e * 4 + 3]);
            }
        }
    }
}

// -------- K2: gather aggregation (no atomics; streaming reads of g_msg) ------
__global__ __launch_bounds__(256) void gather_kernel(const float* __restrict__ h) {
    int t = blockIdx.x * 256 + threadIdx.x;
    int n = t >> 4;
    int q = t & 15;
    if (n >= N_NODES) return;
    int p  = g_rowstart[n];
    int re = g_rowstart[n + 1];
    float4 acc = make_float4(0.f, 0.f, 0.f, 0.f);
    for (; p + 1 < re; p += 2) {
        float4 m0 = __ldcs(reinterpret_cast<const float4*>(&g_msg[(size_t)p * HID + q * 4]));
        float4 m1 = __ldcs(reinterpret_cast<const float4*>(&g_msg[(size_t)(p + 1) * HID + q * 4]));
        int s0 = __ldg(&g_src[p]);
        int s1 = __ldg(&g_src[p + 1]);
        float4 h0 = __ldg(reinterpret_cast<const float4*>(&h[(size_t)s0 * HID + q * 4]));
        float4 h1 = __ldg(reinterpret_cast<const float4*>(&h[(size_t)s1 * HID + q * 4]));
        acc.x += m0.x * h0.x; acc.y += m0.y * h0.y; acc.z += m0.z * h0.z; acc.w += m0.w * h0.w;
        acc.x += m1.x * h1.x; acc.y += m1.y * h1.y; acc.z += m1.z * h1.z; acc.w += m1.w * h1.w;
    }
    if (p < re) {
        float4 m = __ldcs(reinterpret_cast<const float4*>(&g_msg[(size_t)p * HID + q * 4]));
        int s = __ldg(&g_src[p]);
        float4 hv = __ldg(reinterpret_cast<const float4*>(&h[(size_t)s * HID + q * 4]));
        acc.x += m.x * hv.x; acc.y += m.y * hv.y; acc.z += m.z * hv.z; acc.w += m.w * hv.w;
    }
    *reinterpret_cast<float4*>(&g_agg[(size_t)n * HID + q * 4]) = acc;
}

// -------- K3: GRU via f32x2, node-pair accumulators, transposed data tiles ----
#define WPAD 67
#define DPAD 68
#define GRU_TILE 64
#define GRU_SMEM_FLOATS (2 * 192 * WPAD + 2 * GRU_TILE * DPAD)
#define GRU_SMEM_BYTES  (GRU_SMEM_FLOATS * 4)

__global__ __launch_bounds__(512) void gru_kernel(
    const float* __restrict__ Wih, const float* __restrict__ bih,
    const float* __restrict__ Whh, const float* __restrict__ bhh,
    float* __restrict__ h)
{
    extern __shared__ float sm[];
    float* sWih  = sm;                        // [192][WPAD]
    float* sWhh  = sWih + 192 * WPAD;
    float* sAggT = sWhh + 192 * WPAD;         // [64][DPAD]
    float* sHT   = sAggT + GRU_TILE * DPAD;

    const int tid = threadIdx.x;
    const int d = tid & 63;
    const int g = tid >> 6;

    for (int i = tid; i < 192 * 64; i += 512) {
        int r = i >> 6, c = i & 63;
        sWih[r * WPAD + c] = Wih[i];
        sWhh[r * WPAD + c] = Whh[i];
    }
    const float bi_r = __ldg(&bih[d]), bi_z = __ldg(&bih[64 + d]), bi_n = __ldg(&bih[128 + d]);
    const float bh_r = __ldg(&bhh[d]), bh_z = __ldg(&bhh[64 + d]), bh_n = __ldg(&bhh[128 + d]);
    const u64 brz2 = pack2(bi_r + bh_r, bi_r + bh_r);
    const u64 bzz2 = pack2(bi_z + bh_z, bi_z + bh_z);
    const u64 bin2 = pack2(bi_n, bi_n);
    const u64 bhn2 = pack2(bh_n, bh_n);
    __syncthreads();

    const int ntiles = (N_NODES + GRU_TILE - 1) / GRU_TILE;
    for (int tile = blockIdx.x; tile < ntiles; tile += gridDim.x) {
        const int nb = tile * GRU_TILE;
        for (int i = tid; i < GRU_TILE * 64; i += 512) {
            int node = i >> 6, k = i & 63;
            bool ok = (nb + node) < N_NODES;
            size_t gi = (size_t)(nb + node) * 64 + k;
            sAggT[k * DPAD + node] = ok ? g_agg[gi] : 0.f;
            sHT[k * DPAD + node]   = ok ? h[gi] : 0.f;
        }
        __syncthreads();

        u64 acc_r[4], acc_z[4], acc_in[4], acc_hn[4];
        #pragma unroll
        for (int jp = 0; jp < 4; ++jp) {
            acc_r[jp] = brz2; acc_z[jp] = bzz2; acc_in[jp] = bin2; acc_hn[jp] = bhn2;
        }

        #pragma unroll 2
        for (int k = 0; k < 64; ++k) {
            float wir = sWih[d * WPAD + k];
            float wiz = sWih[(64 + d) * WPAD + k];
            float win = sWih[(128 + d) * WPAD + k];
            float whr = sWhh[d * WPAD + k];
            float whz = sWhh[(64 + d) * WPAD + k];
            float whn = sWhh[(128 + d) * WPAD + k];
            u64 wir2 = pack2(wir, wir), wiz2 = pack2(wiz, wiz), win2 = pack2(win, win);
            u64 whr2 = pack2(whr, whr), whz2 = pack2(whz, whz), whn2 = pack2(whn, whn);
            const ulonglong2* aT = reinterpret_cast<const ulonglong2*>(&sAggT[k * DPAD + g * 8]);
            const ulonglong2* hT = reinterpret_cast<const ulonglong2*>(&sHT[k * DPAD + g * 8]);
            #pragma unroll
            for (int jq = 0; jq < 2; ++jq) {
                ulonglong2 aa = aT[jq];
                ulonglong2 hh = hT[jq];
                acc_r[2*jq]   = fma2(wir2, aa.x, acc_r[2*jq]);
                acc_r[2*jq]   = fma2(whr2, hh.x, acc_r[2*jq]);
                acc_z[2*jq]   = fma2(wiz2, aa.x, acc_z[2*jq]);
                acc_z[2*jq]   = fma2(whz2, hh.x, acc_z[2*jq]);
                acc_in[2*jq]  = fma2(win2, aa.x, acc_in[2*jq]);
                acc_hn[2*jq]  = fma2(whn2, hh.x, acc_hn[2*jq]);
                acc_r[2*jq+1] = fma2(wir2, aa.y, acc_r[2*jq+1]);
                acc_r[2*jq+1] = fma2(whr2, hh.y, acc_r[2*jq+1]);
                acc_z[2*jq+1] = fma2(wiz2, aa.y, acc_z[2*jq+1]);
                acc_z[2*jq+1] = fma2(whz2, hh.y, acc_z[2*jq+1]);
                acc_in[2*jq+1]= fma2(win2, aa.y, acc_in[2*jq+1]);
                acc_hn[2*jq+1]= fma2(whn2, hh.y, acc_hn[2*jq+1]);
            }
        }

        #pragma unroll
        for (int jp = 0; jp < 4; ++jp) {
            float r0, r1, z0, z1, n0, n1, hn0, hn1;
            unpack2(acc_r[jp], r0, r1);
            unpack2(acc_z[jp], z0, z1);
            unpack2(acc_in[jp], n0, n1);
            unpack2(acc_hn[jp], hn0, hn1);
            int na = g * 8 + 2 * jp;
            #pragma unroll
            for (int half = 0; half < 2; ++half) {
                int n = na + half;
                if (nb + n < N_NODES) {
                    float rv  = fsigmoid(half ? r1 : r0);
                    float zv  = fsigmoid(half ? z1 : z0);
                    float nnv = ftanh((half ? n1 : n0) + rv * (half ? hn1 : hn0));
                    float hp  = sHT[d * DPAD + n];
                    h[(size_t)(nb + n) * 64 + d] = (1.f - zv) * nnv + zv * hp;
                }
            }
        }
        __syncthreads();
    }
}

// -------- launch --------
extern "C" void kernel_launch(void* const* d_in, const int* in_sizes, int n_in,
                              void* d_out, int out_size)
{
    const float* h0   = (const float*)d_in[0];
    const float* ea   = (const float*)d_in[1];
    const int*   eidx = (const int*)d_in[2];     // int64 inputs arrive as int32
    const float* W1   = (const float*)d_in[3];
    const float* b1   = (const float*)d_in[4];
    const float* W2   = (const float*)d_in[5];
    const float* b2   = (const float*)d_in[6];
    const float* Wih  = (const float*)d_in[7];
    const float* bih  = (const float*)d_in[8];
    const float* Whh  = (const float*)d_in[9];
    const float* bhh  = (const float*)d_in[10];
    float* h = (float*)d_out;

    cudaFuncSetAttribute(gru_kernel, cudaFuncAttributeMaxDynamicSharedMemorySize,
                         GRU_SMEM_BYTES);
    cudaFuncSetAttribute(msg_kernel, cudaFuncAttributeMaxDynamicSharedMemorySize,
                         MSG_SMEM_BYTES);

    void* countPtr = nullptr;
    cudaGetSymbolAddress(&countPtr, g_count);

    cudaMemcpyAsync(h, h0, (size_t)N_NODES * HID * sizeof(float),
                    cudaMemcpyDeviceToDevice, 0);

    // CSR build (edge_index is launch-invariant); scan also transposes weights
    cudaMemsetAsync(countPtr, 0, N_NODES * sizeof(int), 0);
    hist_kernel<<<(N_EDGES + 255) / 256, 256>>>(eidx);
    scan_kernel<<<1, 1024>>>(W1, W2);
    place_kernel<<<(N_EDGES + 255) / 256, 256>>>(eidx);

    // launch slot 6 -> ncu (-s 5 -c 1) captures msg_kernel
    msg_kernel<<<(N_EDGES + ET - 1) / ET, 256, MSG_SMEM_BYTES>>>(ea, b1, b2);

    for (int s = 0; s < NSTEPS; ++s) {
        gather_kernel<<<(N_NODES * 16 + 255) / 256, 256>>>(h);
        gru_kernel<<<152, 512, GRU_SMEM_BYTES>>>(Wih, bih, Whh, bhh, h);
    }
}